// round 11
// baseline (speedup 1.0000x reference)
#include <cuda_runtime.h>
#include <cuda_bf16.h>
#include <math.h>
#include <stdint.h>

// Problem constants
#define B_   2
#define T_   2048
#define C_   1024
#define H_   16
#define M_   (B_ * T_)      // 4096
#define N3C_ (3 * C_)       // 3072
#define KP_  (3 * C_)       // K' = 3*K (triple split)

// ---------------------------------------------------------------------------
// Helpers
// ---------------------------------------------------------------------------
__device__ __forceinline__ uint32_t smem_u32(const void* p) {
    uint32_t a;
    asm("{ .reg .u64 t; cvta.to.shared.u64 t, %1; cvt.u32.u64 %0, t; }"
        : "=r"(a) : "l"(p));
    return a;
}

__device__ __forceinline__ void ldsm_x4(uint32_t (&r)[4], uint32_t addr) {
    asm volatile("ldmatrix.sync.aligned.m8n8.x4.shared.b16 {%0,%1,%2,%3}, [%4];"
                 : "=r"(r[0]), "=r"(r[1]), "=r"(r[2]), "=r"(r[3]) : "r"(addr));
}

__device__ __forceinline__ void ldsm_x4_t(uint32_t (&r)[4], uint32_t addr) {
    asm volatile("ldmatrix.sync.aligned.m8n8.x4.trans.shared.b16 {%0,%1,%2,%3}, [%4];"
                 : "=r"(r[0]), "=r"(r[1]), "=r"(r[2]), "=r"(r[3]) : "r"(addr));
}

__device__ __forceinline__ void mma_bf16(float (&c)[4], const uint32_t (&a)[4],
                                         uint32_t b0, uint32_t b1) {
    asm volatile(
        "mma.sync.aligned.m16n8k16.row.col.f32.bf16.bf16.f32 "
        "{%0,%1,%2,%3}, {%4,%5,%6,%7}, {%8,%9}, {%0,%1,%2,%3};"
        : "+f"(c[0]), "+f"(c[1]), "+f"(c[2]), "+f"(c[3])
        : "r"(a[0]), "r"(a[1]), "r"(a[2]), "r"(a[3]), "r"(b0), "r"(b1));
}

__device__ __forceinline__ uint32_t packbf(float lo, float hi) {
    uint32_t u;
    asm("cvt.rn.bf16x2.f32 %0, %1, %2;" : "=r"(u) : "f"(hi), "f"(lo));
    return u;
}

// ---------------------------------------------------------------------------
// Scratch (device globals)
// ---------------------------------------------------------------------------
__device__ __nv_bfloat16 g_x2[(size_t)M_ * KP_];     // [Ah|Al|Ah] of x
__device__ __nv_bfloat16 g_y2[(size_t)M_ * KP_];     // [Ah|Al|Ah] of attn out
__device__ __nv_bfloat16 g_wa2[(size_t)N3C_ * KP_];  // [Bh|Bh|Bl] of snap(w_attn)
__device__ __nv_bfloat16 g_wp2[(size_t)C_ * KP_];    // [Bh|Bh|Bl] of snap(w_proj)
__device__ __nv_bfloat16 g_qkvh[(size_t)M_ * N3C_];  // qkv hi
__device__ __nv_bfloat16 g_qkvl[(size_t)M_ * N3C_];  // qkv lo
__device__ unsigned int g_maxbits[2];

// ---------------------------------------------------------------------------
// Prologue: zero, fused maxabs, fused snap+cvt (exact argmin, exact division)
// ---------------------------------------------------------------------------
__global__ void zero_scales_kernel() { g_maxbits[0] = 0u; g_maxbits[1] = 0u; }

__device__ __forceinline__ void maxabs_body(const float4* __restrict__ w,
                                            int n4, int slot, int b0, int nb) {
    float m = 0.0f;
    for (int i = b0 * 256 + threadIdx.x; i < n4; i += nb * 256) {
        float4 v = w[i];
        m = fmaxf(m, fmaxf(fmaxf(fabsf(v.x), fabsf(v.y)),
                           fmaxf(fabsf(v.z), fabsf(v.w))));
    }
    #pragma unroll
    for (int o = 16; o > 0; o >>= 1)
        m = fmaxf(m, __shfl_xor_sync(0xffffffffu, m, o));
    __shared__ float sm[8];
    int lane = threadIdx.x & 31, wd = threadIdx.x >> 5;
    if (lane == 0) sm[wd] = m;
    __syncthreads();
    if (threadIdx.x < 8) {
        m = sm[threadIdx.x];
        #pragma unroll
        for (int o = 4; o > 0; o >>= 1)
            m = fmaxf(m, __shfl_xor_sync(0xffu, m, o));
        if (threadIdx.x == 0)
            atomicMax(&g_maxbits[slot], __float_as_uint(m));
    }
}

__global__ void __launch_bounds__(256) maxabs_fused(const float4* __restrict__ wa,
                                                    const float4* __restrict__ wp) {
    const int bx = blockIdx.x;
    if (bx < 384) maxabs_body(wa, (N3C_ * C_) / 4, 0, bx, 384);
    else          maxabs_body(wp, (C_ * C_) / 4, 1, bx - 384, 128);
}

// exact argmin over the 16-entry LUT (reference order, strict < tie-break)
__device__ __forceinline__ float snap1(float wn, float scale) {
    const float L1 = 1.0f,      L3 = 0.5f,      L5 = 0.333333f, L7 = 0.2f,
                L9 = 0.142857f, L11 = 0.090909f, L13 = 0.076923f;
    float bd = fabsf(wn);       // LUT[0] = 0
    float bv = 0.0f;
    #define TRY_(val) { float d_ = fabsf(wn - (val)); if (d_ < bd) { bd = d_; bv = (val); } }
    TRY_(L1)  TRY_(-L1)  TRY_(L3)  TRY_(-L3)  TRY_(L5)  TRY_(-L5)  TRY_(L7)
    TRY_(-L7) TRY_(L9)   TRY_(-L9) TRY_(L11)  TRY_(-L11) TRY_(L13) TRY_(-L13)
    #undef TRY_
    return bv * scale;
}

__device__ __forceinline__ void snap_body(const float4* __restrict__ w,
                                          __nv_bfloat16* __restrict__ out,
                                          int n4, int slot, int b0, int nb) {
    const float scale = __uint_as_float(g_maxbits[slot]) + 1e-6f;
    for (int i = b0 * 256 + threadIdx.x; i < n4; i += nb * 256) {
        float4 wv = w[i];
        float v0 = snap1(wv.x / scale, scale);
        float v1 = snap1(wv.y / scale, scale);
        float v2 = snap1(wv.z / scale, scale);
        float v3 = snap1(wv.w / scale, scale);
        __nv_bfloat16 h0 = __float2bfloat16(v0), h1 = __float2bfloat16(v1);
        __nv_bfloat16 h2 = __float2bfloat16(v2), h3 = __float2bfloat16(v3);
        uint32_t hp0 = ((uint32_t)__bfloat16_as_ushort(h1) << 16) | __bfloat16_as_ushort(h0);
        uint32_t hp1 = ((uint32_t)__bfloat16_as_ushort(h3) << 16) | __bfloat16_as_ushort(h2);
        uint32_t lp0 = packbf(v0 - __bfloat162float(h0), v1 - __bfloat162float(h1));
        uint32_t lp1 = packbf(v2 - __bfloat162float(h2), v3 - __bfloat162float(h3));
        int r = i >> 8, k = (i & 255) << 2;
        size_t base = (size_t)r * KP_;
        uint2 hp = make_uint2(hp0, hp1), lp = make_uint2(lp0, lp1);
        *(uint2*)(out + base + k)        = hp;   // [hi | hi | lo]
        *(uint2*)(out + base + 1024 + k) = hp;
        *(uint2*)(out + base + 2048 + k) = lp;
    }
}

__device__ __forceinline__ void cvt_body(const float4* __restrict__ a,
                                         __nv_bfloat16* __restrict__ out,
                                         int n4, int b0, int nb) {
    for (int i = b0 * 256 + threadIdx.x; i < n4; i += nb * 256) {
        float4 v = a[i];
        __nv_bfloat16 h0 = __float2bfloat16(v.x), h1 = __float2bfloat16(v.y);
        __nv_bfloat16 h2 = __float2bfloat16(v.z), h3 = __float2bfloat16(v.w);
        uint32_t hp0 = ((uint32_t)__bfloat16_as_ushort(h1) << 16) | __bfloat16_as_ushort(h0);
        uint32_t hp1 = ((uint32_t)__bfloat16_as_ushort(h3) << 16) | __bfloat16_as_ushort(h2);
        uint32_t lp0 = packbf(v.x - __bfloat162float(h0), v.y - __bfloat162float(h1));
        uint32_t lp1 = packbf(v.z - __bfloat162float(h2), v.w - __bfloat162float(h3));
        int r = i >> 8, k = (i & 255) << 2;
        size_t base = (size_t)r * KP_;
        uint2 hp = make_uint2(hp0, hp1), lp = make_uint2(lp0, lp1);
        *(uint2*)(out + base + k)        = hp;   // [hi | lo | hi]
        *(uint2*)(out + base + 1024 + k) = lp;
        *(uint2*)(out + base + 2048 + k) = hp;
    }
}

__global__ void __launch_bounds__(256) prep_fused(
    const float4* __restrict__ wa, const float4* __restrict__ wp,
    const float4* __restrict__ x,
    __nv_bfloat16* __restrict__ wa2, __nv_bfloat16* __restrict__ wp2,
    __nv_bfloat16* __restrict__ x2)
{
    const int bx = blockIdx.x;
    if (bx < 512)       snap_body(wa, wa2, (N3C_ * C_) / 4, 0, bx, 512);
    else if (bx < 640)  snap_body(wp, wp2, (C_ * C_) / 4, 1, bx - 512, 128);
    else                cvt_body(x, x2, (M_ * C_) / 4, bx - 640, 512);
}

// ---------------------------------------------------------------------------
// bf16 mma.sync GEMM: 128x128 tile, BK=64, 8 warps (2m x 4n), double-buffered
// dynamic smem (73.7KB, occ 2), two-wave register staging (16 regs live).
// SPLIT=1: bf16 hi/lo out; SPLIT=0: fp32 out.
// ---------------------------------------------------------------------------
#define GPAD_ 144
#define GBUF_ (128 * GPAD_)          // 18432 per matrix per stage
#define GSTG_ (2 * GBUF_)            // 36864 per stage (A+B)
#define GEMM_SMEM (2 * GSTG_)        // 73728
#define GNIT_ 48                     // 3072 / 64

template <int SPLIT>
__global__ void __launch_bounds__(256, 2)
gemm_mma(const __nv_bfloat16* __restrict__ A2, const __nv_bfloat16* __restrict__ B2,
         const float* __restrict__ bias, float* __restrict__ Cf,
         __nv_bfloat16* __restrict__ Chi, __nv_bfloat16* __restrict__ Clo, int Nd)
{
    extern __shared__ char gsm[];
    const uint32_t sbase = smem_u32(gsm);
    const int tid  = threadIdx.x;
    const int lane = tid & 31;
    const int wid  = tid >> 5;
    const int wm   = wid >> 2;
    const int wn   = wid & 3;
    const int m0   = blockIdx.y * 128;
    const int n0   = blockIdx.x * 128;

    // loader: 2 threads per row; each covers 4 x 16B chunks
    const int lr = tid >> 1;
    const int lc = (tid & 1) * 4;                 // chunk base 0 or 4
    const __nv_bfloat16* gA = A2 + (size_t)(m0 + lr) * KP_;
    const __nv_bfloat16* gB = B2 + (size_t)(n0 + lr) * KP_;
    const uint32_t soff = (uint32_t)(lr * GPAD_ + lc * 16);

    const uint32_t aoff = (uint32_t)((wm * 64 + (lane & 15)) * GPAD_ + (lane >> 4) * 16);
    const uint32_t boff = (uint32_t)((wn * 32 + (lane & 7) + ((lane >> 4) & 1) * 8) * GPAD_
                                     + ((lane >> 3) & 1) * 16);

    float acc[4][4][4] = {};

    // preload stage 0 (two waves)
    {
        uint4 t[4];
        #pragma unroll
        for (int c = 0; c < 4; ++c) t[c] = *(const uint4*)(gA + (lc + c) * 8);
        #pragma unroll
        for (int c = 0; c < 4; ++c) *(uint4*)(gsm + soff + c * 16) = t[c];
        #pragma unroll
        for (int c = 0; c < 4; ++c) t[c] = *(const uint4*)(gB + (lc + c) * 8);
        #pragma unroll
        for (int c = 0; c < 4; ++c) *(uint4*)(gsm + GBUF_ + soff + c * 16) = t[c];
    }
    __syncthreads();

    for (int it = 0; it < GNIT_; ++it) {
        const uint32_t bA = sbase + (it & 1) * GSTG_;
        const uint32_t bB = bA + GBUF_;
        char* dA = gsm + ((it + 1) & 1) * GSTG_ + soff;
        char* dB = dA + GBUF_;
        const bool pf = (it + 1 < GNIT_);
        const __nv_bfloat16* gAn = gA + (it + 1) * 64;
        const __nv_bfloat16* gBn = gB + (it + 1) * 64;

        uint4 st4[4];
        if (pf) {
            #pragma unroll
            for (int c = 0; c < 4; ++c) st4[c] = *(const uint4*)(gAn + (lc + c) * 8);
        }

        // ks 0,1
        #pragma unroll
        for (int ks = 0; ks < 2; ++ks) {
            uint32_t af[4][4];
            #pragma unroll
            for (int mt = 0; mt < 4; ++mt)
                ldsm_x4(af[mt], bA + aoff + mt * (16 * GPAD_) + ks * 32);
            #pragma unroll
            for (int p = 0; p < 2; ++p) {
                uint32_t bf[4];
                ldsm_x4(bf, bB + boff + p * (16 * GPAD_) + ks * 32);
                #pragma unroll
                for (int mt = 0; mt < 4; ++mt) {
                    mma_bf16(acc[mt][2 * p],     af[mt], bf[0], bf[1]);
                    mma_bf16(acc[mt][2 * p + 1], af[mt], bf[2], bf[3]);
                }
            }
        }

        if (pf) {
            #pragma unroll
            for (int c = 0; c < 4; ++c) *(uint4*)(dA + c * 16) = st4[c];
            #pragma unroll
            for (int c = 0; c < 4; ++c) st4[c] = *(const uint4*)(gBn + (lc + c) * 8);
        }

        // ks 2,3
        #pragma unroll
        for (int ks = 2; ks < 4; ++ks) {
            uint32_t af[4][4];
            #pragma unroll
            for (int mt = 0; mt < 4; ++mt)
                ldsm_x4(af[mt], bA + aoff + mt * (16 * GPAD_) + ks * 32);
            #pragma unroll
            for (int p = 0; p < 2; ++p) {
                uint32_t bf[4];
                ldsm_x4(bf, bB + boff + p * (16 * GPAD_) + ks * 32);
                #pragma unroll
                for (int mt = 0; mt < 4; ++mt) {
                    mma_bf16(acc[mt][2 * p],     af[mt], bf[0], bf[1]);
                    mma_bf16(acc[mt][2 * p + 1], af[mt], bf[2], bf[3]);
                }
            }
        }

        if (pf) {
            #pragma unroll
            for (int c = 0; c < 4; ++c) *(uint4*)(dB + c * 16) = st4[c];
            __syncthreads();
        }
    }

    #pragma unroll
    for (int nt = 0; nt < 4; ++nt) {
        const int col = n0 + wn * 32 + nt * 8 + (lane & 3) * 2;
        const float bv0 = bias[col];
        const float bv1 = bias[col + 1];
        #pragma unroll
        for (int mt = 0; mt < 4; ++mt) {
            const int row = m0 + wm * 64 + mt * 16 + (lane >> 2);
            float v0 = acc[mt][nt][0] + bv0, v1 = acc[mt][nt][1] + bv1;
            float v2 = acc[mt][nt][2] + bv0, v3 = acc[mt][nt][3] + bv1;
            if (SPLIT) {
                __nv_bfloat16 h0 = __float2bfloat16(v0), h1 = __float2bfloat16(v1);
                __nv_bfloat16 h2 = __float2bfloat16(v2), h3 = __float2bfloat16(v3);
                uint32_t hp0 = ((uint32_t)__bfloat16_as_ushort(h1) << 16) | __bfloat16_as_ushort(h0);
                uint32_t hp1 = ((uint32_t)__bfloat16_as_ushort(h3) << 16) | __bfloat16_as_ushort(h2);
                uint32_t lp0 = packbf(v0 - __bfloat162float(h0), v1 - __bfloat162float(h1));
                uint32_t lp1 = packbf(v2 - __bfloat162float(h2), v3 - __bfloat162float(h3));
                *(uint32_t*)(Chi + (size_t)row * Nd + col)       = hp0;
                *(uint32_t*)(Chi + (size_t)(row + 8) * Nd + col) = hp1;
                *(uint32_t*)(Clo + (size_t)row * Nd + col)       = lp0;
                *(uint32_t*)(Clo + (size_t)(row + 8) * Nd + col) = lp1;
            } else {
                float2 o0, o1;
                o0.x = v0; o0.y = v1;
                o1.x = v2; o1.y = v3;
                *(float2*)&Cf[(size_t)row * Nd + col]       = o0;
                *(float2*)&Cf[(size_t)(row + 8) * Nd + col] = o1;
            }
        }
    }
}

// ---------------------------------------------------------------------------
// Tensor-core causal flash attention (unchanged, proven): bf16 split HMMA,
// 128-q tile, 8 warps x 16 rows, 64-key tiles double-buffered.
// Writes y directly in triple-split layout [hi|lo|hi] into g_y2.
// ---------------------------------------------------------------------------
#define SQH_  0
#define SQL_  (128 * 144)            // 18432
#define SKV0_ (2 * 128 * 144)        // 36864
#define KVBUF_ (4 * 64 * 144)        // 36864 (KH, KL, VH, VL)
#define ATTN_SMEM (SKV0_ + 2 * KVBUF_)   // 110592

__global__ void __launch_bounds__(256, 1)
attn_mma(const __nv_bfloat16* __restrict__ qh_g, const __nv_bfloat16* __restrict__ ql_g,
         __nv_bfloat16* __restrict__ y2)
{
    extern __shared__ char sm[];
    const uint32_t base = smem_u32(sm);
    const int tid  = threadIdx.x;
    const int lane = tid & 31;
    const int wid  = tid >> 5;
    const int qt   = (int)gridDim.x - 1 - (int)blockIdx.x;   // long blocks first
    const int bh   = blockIdx.y;
    const int bb   = bh >> 4;
    const int h    = bh & 15;
    const int qbase = qt * 128;

    // ---- load Q tile hi/lo into smem ----
    {
        const int r  = tid >> 1;
        const int c0 = (tid & 1) * 4;
        const size_t ro = ((size_t)(bb * T_ + qbase + r)) * 3072 + h * 64;
        const uint4* sh = (const uint4*)(qh_g + ro) + c0;
        const uint4* sl = (const uint4*)(ql_g + ro) + c0;
        #pragma unroll
        for (int c = 0; c < 4; ++c) {
            *(uint4*)(sm + SQH_ + r * 144 + (c0 + c) * 16) = sh[c];
            *(uint4*)(sm + SQL_ + r * 144 + (c0 + c) * 16) = sl[c];
        }
    }
    __syncthreads();

    // ---- Q fragments resident in registers for all k tiles ----
    const uint32_t aoff = (uint32_t)((wid * 16 + (lane & 15)) * 144 + (lane >> 4) * 16);
    uint32_t qhf[4][4], qlf[4][4];
    #pragma unroll
    for (int kc = 0; kc < 4; ++kc) {
        ldsm_x4(qhf[kc], base + SQH_ + aoff + kc * 32);
        ldsm_x4(qlf[kc], base + SQL_ + aoff + kc * 32);
    }

    // KV loader mapping: 64 rows x 8 uint4, 256 threads -> 2 uint4/thread/subtile
    const int kr  = tid >> 2;
    const int kc4 = (tid & 3) * 2;
    const int ckq = (1024 + h * 64) >> 3;
    const int cvq = (2048 + h * 64) >> 3;

    float mrow0 = -INFINITY, mrow1 = -INFINITY, lr0 = 0.0f, lr1 = 0.0f;
    float accO[8][4] = {};

    const int nkt = 2 * qt + 2;
    const int qwbase = qbase + wid * 16;
    const int r0g = qwbase + (lane >> 2);
    const float sc = 0.125f;   // 1/sqrt(64)

    uint4 stage[8];
    // load + store tile 0
    {
        const size_t ro = ((size_t)(bb * T_ + kr)) * 3072;
        const uint4* ph = (const uint4*)(qh_g + ro);
        const uint4* pl = (const uint4*)(ql_g + ro);
        stage[0] = ph[ckq + kc4]; stage[1] = ph[ckq + kc4 + 1];
        stage[2] = pl[ckq + kc4]; stage[3] = pl[ckq + kc4 + 1];
        stage[4] = ph[cvq + kc4]; stage[5] = ph[cvq + kc4 + 1];
        stage[6] = pl[cvq + kc4]; stage[7] = pl[cvq + kc4 + 1];
        char* d = sm + SKV0_ + kr * 144 + kc4 * 16;
        *(uint4*)(d)             = stage[0]; *(uint4*)(d + 16)         = stage[1];
        *(uint4*)(d + 9216)      = stage[2]; *(uint4*)(d + 9216 + 16)  = stage[3];
        *(uint4*)(d + 18432)     = stage[4]; *(uint4*)(d + 18432 + 16) = stage[5];
        *(uint4*)(d + 27648)     = stage[6]; *(uint4*)(d + 27648 + 16) = stage[7];
    }
    __syncthreads();

    for (int j = 0; j < nkt; ++j) {
        const int buf = j & 1;
        const int kbase = j * 64;

        if (j + 1 < nkt) {   // prefetch next tile into registers
            const size_t ro = ((size_t)(bb * T_ + (j + 1) * 64 + kr)) * 3072;
            const uint4* ph = (const uint4*)(qh_g + ro);
            const uint4* pl = (const uint4*)(ql_g + ro);
            stage[0] = ph[ckq + kc4]; stage[1] = ph[ckq + kc4 + 1];
            stage[2] = pl[ckq + kc4]; stage[3] = pl[ckq + kc4 + 1];
            stage[4] = ph[cvq + kc4]; stage[5] = ph[cvq + kc4 + 1];
            stage[6] = pl[cvq + kc4]; stage[7] = pl[cvq + kc4 + 1];
        }

        if (kbase <= qwbase + 15) {   // per-warp causal skip
            const uint32_t kvb = base + SKV0_ + buf * KVBUF_;

            // ---- S = Q K^T (3-term split) ----
            float sa[8][4];
            #pragma unroll
            for (int nt = 0; nt < 8; ++nt)
                #pragma unroll
                for (int i = 0; i < 4; ++i) sa[nt][i] = 0.0f;

            #pragma unroll
            for (int kc = 0; kc < 4; ++kc) {
                #pragma unroll
                for (int p = 0; p < 4; ++p) {
                    const uint32_t bo = (uint32_t)((p * 16 + (lane & 7) + ((lane >> 4) & 1) * 8) * 144
                                                   + ((lane >> 3) & 1) * 16 + kc * 32);
                    uint32_t kh[4], kl[4];
                    ldsm_x4(kh, kvb + bo);
                    ldsm_x4(kl, kvb + 9216 + bo);
                    mma_bf16(sa[2 * p],     qhf[kc], kh[0], kh[1]);
                    mma_bf16(sa[2 * p + 1], qhf[kc], kh[2], kh[3]);
                    mma_bf16(sa[2 * p],     qlf[kc], kh[0], kh[1]);
                    mma_bf16(sa[2 * p + 1], qlf[kc], kh[2], kh[3]);
                    mma_bf16(sa[2 * p],     qhf[kc], kl[0], kl[1]);
                    mma_bf16(sa[2 * p + 1], qhf[kc], kl[2], kl[3]);
                }
            }

            // ---- online softmax ----
            const bool diag = (kbase + 63 > qwbase);
            float mx0 = -INFINITY, mx1 = -INFINITY;
            #pragma unroll
            for (int nt = 0; nt < 8; ++nt) {
                const int col = kbase + nt * 8 + (lane & 3) * 2;
                float s0 = sa[nt][0] * sc, s1 = sa[nt][1] * sc;
                float s2 = sa[nt][2] * sc, s3 = sa[nt][3] * sc;
                if (diag) {
                    if (col     > r0g)     s0 = -INFINITY;
                    if (col + 1 > r0g)     s1 = -INFINITY;
                    if (col     > r0g + 8) s2 = -INFINITY;
                    if (col + 1 > r0g + 8) s3 = -INFINITY;
                }
                sa[nt][0] = s0; sa[nt][1] = s1; sa[nt][2] = s2; sa[nt][3] = s3;
                mx0 = fmaxf(mx0, fmaxf(s0, s1));
                mx1 = fmaxf(mx1, fmaxf(s2, s3));
            }
            mx0 = fmaxf(mx0, __shfl_xor_sync(0xffffffffu, mx0, 1));
            mx0 = fmaxf(mx0, __shfl_xor_sync(0xffffffffu, mx0, 2));
            mx1 = fmaxf(mx1, __shfl_xor_sync(0xffffffffu, mx1, 1));
            mx1 = fmaxf(mx1, __shfl_xor_sync(0xffffffffu, mx1, 2));

            const float mn0 = fmaxf(mrow0, mx0), mn1 = fmaxf(mrow1, mx1);
            const float f0 = __expf(mrow0 - mn0), f1 = __expf(mrow1 - mn1);
            mrow0 = mn0; mrow1 = mn1;

            float sum0 = 0.0f, sum1 = 0.0f;
            #pragma unroll
            for (int nt = 0; nt < 8; ++nt) {
                float p0 = __expf(sa[nt][0] - mn0);
                float p1 = __expf(sa[nt][1] - mn0);
                float p2 = __expf(sa[nt][2] - mn1);
                float p3 = __expf(sa[nt][3] - mn1);
                sa[nt][0] = p0; sa[nt][1] = p1; sa[nt][2] = p2; sa[nt][3] = p3;
                sum0 += p0 + p1;
                sum1 += p2 + p3;
            }
            sum0 += __shfl_xor_sync(0xffffffffu, sum0, 1);
            sum0 += __shfl_xor_sync(0xffffffffu, sum0, 2);
            sum1 += __shfl_xor_sync(0xffffffffu, sum1, 1);
            sum1 += __shfl_xor_sync(0xffffffffu, sum1, 2);
            lr0 = lr0 * f0 + sum0;
            lr1 = lr1 * f1 + sum1;
            #pragma unroll
            for (int nt = 0; nt < 8; ++nt) {
                accO[nt][0] *= f0; accO[nt][1] *= f0;
                accO[nt][2] *= f1; accO[nt][3] *= f1;
            }

            // ---- P -> A-fragments (register repack, exact hi/lo split) ----
            uint32_t phf[4][4], plf[4][4];
            #pragma unroll
            for (int kc = 0; kc < 4; ++kc) {
                #pragma unroll
                for (int half = 0; half < 2; ++half) {
                    const int nt = 2 * kc + half;
                    float v0 = sa[nt][0], v1 = sa[nt][1];
                    float v2 = sa[nt][2], v3 = sa[nt][3];
                    __nv_bfloat16 h0 = __float2bfloat16(v0), h1 = __float2bfloat16(v1);
                    __nv_bfloat16 h2 = __float2bfloat16(v2), h3 = __float2bfloat16(v3);
                    phf[kc][half * 2 + 0] = ((uint32_t)__bfloat16_as_ushort(h1) << 16)
                                            | __bfloat16_as_ushort(h0);
                    phf[kc][half * 2 + 1] = ((uint32_t)__bfloat16_as_ushort(h3) << 16)
                                            | __bfloat16_as_ushort(h2);
                    plf[kc][half * 2 + 0] = packbf(v0 - __bfloat162float(h0),
                                                   v1 - __bfloat162float(h1));
                    plf[kc][half * 2 + 1] = packbf(v2 - __bfloat162float(h2),
                                                   v3 - __bfloat162float(h3));
                }
            }

            // ---- accO += P V (3-term split, ldmatrix.trans on V) ----
            const uint32_t voff = (uint32_t)((lane & 15) * 144 + (lane >> 4) * 16);
            #pragma unroll
            for (int kc = 0; kc < 4; ++kc) {
                #pragma unroll
                for (int np = 0; np < 4; ++np) {
                    uint32_t vh[4], vl[4];
                    const uint32_t va = kvb + voff + kc * (16 * 144) + np * 32;
                    ldsm_x4_t(vh, va + 18432);
                    ldsm_x4_t(vl, va + 27648);
                    mma_bf16(accO[2 * np],     phf[kc], vh[0], vh[1]);
                    mma_bf16(accO[2 * np + 1], phf[kc], vh[2], vh[3]);
                    mma_bf16(accO[2 * np],     plf[kc], vh[0], vh[1]);
                    mma_bf16(accO[2 * np + 1], plf[kc], vh[2], vh[3]);
                    mma_bf16(accO[2 * np],     phf[kc], vl[0], vl[1]);
                    mma_bf16(accO[2 * np + 1], phf[kc], vl[2], vl[3]);
                }
            }
        }

        if (j + 1 < nkt) {   // store prefetched tile into the other buffer
            char* d = sm + SKV0_ + (1 - buf) * KVBUF_ + kr * 144 + kc4 * 16;
            *(uint4*)(d)             = stage[0]; *(uint4*)(d + 16)         = stage[1];
            *(uint4*)(d + 9216)      = stage[2]; *(uint4*)(d + 9216 + 16)  = stage[3];
            *(uint4*)(d + 18432)     = stage[4]; *(uint4*)(d + 18432 + 16) = stage[5];
            *(uint4*)(d + 27648)     = stage[6]; *(uint4*)(d + 27648 + 16) = stage[7];
        }
        __syncthreads();
    }

    // ---- epilogue: normalize, write triple-split [hi|lo|hi] to y2 ----
    const float inv0 = 1.0f / lr0, inv1 = 1.0f / lr1;
    const size_t row0 = (size_t)(bb * T_ + qwbase + (lane >> 2));
    const int colb = h * 64 + (lane & 3) * 2;
    #pragma unroll
    for (int nt = 0; nt < 8; ++nt) {
        const int col = colb + nt * 8;
        float v0 = accO[nt][0] * inv0, v1 = accO[nt][1] * inv0;
        float v2 = accO[nt][2] * inv1, v3 = accO[nt][3] * inv1;
        __nv_bfloat16 h0 = __float2bfloat16(v0), h1 = __float2bfloat16(v1);
        __nv_bfloat16 h2 = __float2bfloat16(v2), h3 = __float2bfloat16(v3);
        uint32_t hp0 = ((uint32_t)__bfloat16_as_ushort(h1) << 16) | __bfloat16_as_ushort(h0);
        uint32_t hp1 = ((uint32_t)__bfloat16_as_ushort(h3) << 16) | __bfloat16_as_ushort(h2);
        uint32_t lp0 = packbf(v0 - __bfloat162float(h0), v1 - __bfloat162float(h1));
        uint32_t lp1 = packbf(v2 - __bfloat162float(h2), v3 - __bfloat162float(h3));
        *(uint32_t*)(y2 + row0 * 3072 + col)              = hp0;
        *(uint32_t*)(y2 + row0 * 3072 + 1024 + col)       = lp0;
        *(uint32_t*)(y2 + row0 * 3072 + 2048 + col)       = hp0;
        *(uint32_t*)(y2 + (row0 + 8) * 3072 + col)        = hp1;
        *(uint32_t*)(y2 + (row0 + 8) * 3072 + 1024 + col) = lp1;
        *(uint32_t*)(y2 + (row0 + 8) * 3072 + 2048 + col) = hp1;
    }
}

// ---------------------------------------------------------------------------
// Launch
// ---------------------------------------------------------------------------
extern "C" void kernel_launch(void* const* d_in, const int* in_sizes, int n_in,
                              void* d_out, int out_size)
{
    (void)in_sizes; (void)n_in; (void)out_size;
    const float* x      = (const float*)d_in[0];
    const float* w_attn = (const float*)d_in[1];
    const float* b_attn = (const float*)d_in[2];
    const float* w_proj = (const float*)d_in[3];
    const float* b_proj = (const float*)d_in[4];
    float* out = (float*)d_out;

    __nv_bfloat16 *x2, *y2, *wa2, *wp2, *qkvh, *qkvl;
    cudaGetSymbolAddress((void**)&x2,   g_x2);
    cudaGetSymbolAddress((void**)&y2,   g_y2);
    cudaGetSymbolAddress((void**)&wa2,  g_wa2);
    cudaGetSymbolAddress((void**)&wp2,  g_wp2);
    cudaGetSymbolAddress((void**)&qkvh, g_qkvh);
    cudaGetSymbolAddress((void**)&qkvl, g_qkvl);

    cudaFuncSetAttribute(attn_mma, cudaFuncAttributeMaxDynamicSharedMemorySize,
                         ATTN_SMEM);
    cudaFuncSetAttribute(gemm_mma<1>, cudaFuncAttributeMaxDynamicSharedMemorySize,
                         GEMM_SMEM);
    cudaFuncSetAttribute(gemm_mma<0>, cudaFuncAttributeMaxDynamicSharedMemorySize,
                         GEMM_SMEM);

    // 1) prologue: scales, snap -> [hi|hi|lo], x -> [hi|lo|hi]
    zero_scales_kernel<<<1, 1>>>();
    maxabs_fused<<<512, 256>>>((const float4*)w_attn, (const float4*)w_proj);
    prep_fused<<<1152, 256>>>((const float4*)w_attn, (const float4*)w_proj,
                              (const float4*)x, wa2, wp2, x2);

    // 2) qkv = x @ snap(w_attn)^T + b_attn  -> bf16 hi/lo
    gemm_mma<1><<<dim3(N3C_ / 128, M_ / 128), 256, GEMM_SMEM>>>(
        x2, wa2, b_attn, nullptr, qkvh, qkvl, N3C_);

    // 3) tensor-core causal flash attention -> y2 (triple split)
    attn_mma<<<dim3(T_ / 128, B_ * H_), 256, ATTN_SMEM>>>(qkvh, qkvl, y2);

    // 4) out = y @ snap(w_proj)^T + b_proj  (fp32 out)
    gemm_mma<0><<<dim3(C_ / 128, M_ / 128), 256, GEMM_SMEM>>>(
        y2, wp2, b_proj, out, nullptr, nullptr, C_);
}

// round 12
// speedup vs baseline: 1.1503x; 1.1503x over previous
#include <cuda_runtime.h>
#include <cuda_bf16.h>
#include <math.h>
#include <stdint.h>

// Problem constants
#define B_   2
#define T_   2048
#define C_   1024
#define H_   16
#define M_   (B_ * T_)      // 4096
#define N3C_ (3 * C_)       // 3072
#define KD2_ 2048           // [hi|lo] packed K width

// ---------------------------------------------------------------------------
// Helpers
// ---------------------------------------------------------------------------
__device__ __forceinline__ uint32_t smem_u32(const void* p) {
    uint32_t a;
    asm("{ .reg .u64 t; cvta.to.shared.u64 t, %1; cvt.u32.u64 %0, t; }"
        : "=r"(a) : "l"(p));
    return a;
}

__device__ __forceinline__ void ldsm_x4(uint32_t (&r)[4], uint32_t addr) {
    asm volatile("ldmatrix.sync.aligned.m8n8.x4.shared.b16 {%0,%1,%2,%3}, [%4];"
                 : "=r"(r[0]), "=r"(r[1]), "=r"(r[2]), "=r"(r[3]) : "r"(addr));
}

__device__ __forceinline__ void ldsm_x4_t(uint32_t (&r)[4], uint32_t addr) {
    asm volatile("ldmatrix.sync.aligned.m8n8.x4.trans.shared.b16 {%0,%1,%2,%3}, [%4];"
                 : "=r"(r[0]), "=r"(r[1]), "=r"(r[2]), "=r"(r[3]) : "r"(addr));
}

__device__ __forceinline__ void mma_bf16(float (&c)[4], const uint32_t (&a)[4],
                                         uint32_t b0, uint32_t b1) {
    asm volatile(
        "mma.sync.aligned.m16n8k16.row.col.f32.bf16.bf16.f32 "
        "{%0,%1,%2,%3}, {%4,%5,%6,%7}, {%8,%9}, {%0,%1,%2,%3};"
        : "+f"(c[0]), "+f"(c[1]), "+f"(c[2]), "+f"(c[3])
        : "r"(a[0]), "r"(a[1]), "r"(a[2]), "r"(a[3]), "r"(b0), "r"(b1));
}

__device__ __forceinline__ uint32_t packbf(float lo, float hi) {
    uint32_t u;
    asm("cvt.rn.bf16x2.f32 %0, %1, %2;" : "=r"(u) : "f"(hi), "f"(lo));
    return u;
}

__device__ __forceinline__ void cp16(uint32_t dst, const void* src) {
    asm volatile("cp.async.cg.shared.global [%0], [%1], 16;"
                 :: "r"(dst), "l"(src) : "memory");
}
#define CP_COMMIT() asm volatile("cp.async.commit_group;" ::: "memory")
#define CP_WAIT1()  asm volatile("cp.async.wait_group 1;" ::: "memory")
#define CP_WAIT0()  asm volatile("cp.async.wait_group 0;" ::: "memory")

// ---------------------------------------------------------------------------
// Scratch (device globals)
// ---------------------------------------------------------------------------
__device__ __nv_bfloat16 g_x2[(size_t)M_ * KD2_];    // x  [hi|lo]
__device__ __nv_bfloat16 g_y2[(size_t)M_ * KD2_];    // attn out [hi|lo]
__device__ __nv_bfloat16 g_wa2[(size_t)N3C_ * KD2_]; // snap(w_attn) [hi|lo]
__device__ __nv_bfloat16 g_wp2[(size_t)C_ * KD2_];   // snap(w_proj) [hi|lo]
__device__ __nv_bfloat16 g_qkvh[(size_t)M_ * N3C_];  // qkv hi
__device__ __nv_bfloat16 g_qkvl[(size_t)M_ * N3C_];  // qkv lo
__device__ unsigned int g_maxbits[2];

// ---------------------------------------------------------------------------
// Prologue (exact argmin + exact division; [hi|lo] outputs)
// ---------------------------------------------------------------------------
__global__ void zero_scales_kernel() { g_maxbits[0] = 0u; g_maxbits[1] = 0u; }

__device__ __forceinline__ void maxabs_body(const float4* __restrict__ w,
                                            int n4, int slot, int b0, int nb) {
    float m = 0.0f;
    for (int i = b0 * 256 + threadIdx.x; i < n4; i += nb * 256) {
        float4 v = w[i];
        m = fmaxf(m, fmaxf(fmaxf(fabsf(v.x), fabsf(v.y)),
                           fmaxf(fabsf(v.z), fabsf(v.w))));
    }
    #pragma unroll
    for (int o = 16; o > 0; o >>= 1)
        m = fmaxf(m, __shfl_xor_sync(0xffffffffu, m, o));
    __shared__ float sm[8];
    int lane = threadIdx.x & 31, wd = threadIdx.x >> 5;
    if (lane == 0) sm[wd] = m;
    __syncthreads();
    if (threadIdx.x < 8) {
        m = sm[threadIdx.x];
        #pragma unroll
        for (int o = 4; o > 0; o >>= 1)
            m = fmaxf(m, __shfl_xor_sync(0xffu, m, o));
        if (threadIdx.x == 0)
            atomicMax(&g_maxbits[slot], __float_as_uint(m));
    }
}

__global__ void __launch_bounds__(256) maxabs_fused(const float4* __restrict__ wa,
                                                    const float4* __restrict__ wp) {
    const int bx = blockIdx.x;
    if (bx < 384) maxabs_body(wa, (N3C_ * C_) / 4, 0, bx, 384);
    else          maxabs_body(wp, (C_ * C_) / 4, 1, bx - 384, 128);
}

// exact argmin over the 16-entry LUT (reference order, strict < tie-break)
__device__ __forceinline__ float snap1(float wn, float scale) {
    const float L1 = 1.0f,      L3 = 0.5f,      L5 = 0.333333f, L7 = 0.2f,
                L9 = 0.142857f, L11 = 0.090909f, L13 = 0.076923f;
    float bd = fabsf(wn);       // LUT[0] = 0
    float bv = 0.0f;
    #define TRY_(val) { float d_ = fabsf(wn - (val)); if (d_ < bd) { bd = d_; bv = (val); } }
    TRY_(L1)  TRY_(-L1)  TRY_(L3)  TRY_(-L3)  TRY_(L5)  TRY_(-L5)  TRY_(L7)
    TRY_(-L7) TRY_(L9)   TRY_(-L9) TRY_(L11)  TRY_(-L11) TRY_(L13) TRY_(-L13)
    #undef TRY_
    return bv * scale;
}

__device__ __forceinline__ void snap_body(const float4* __restrict__ w,
                                          __nv_bfloat16* __restrict__ out,
                                          int n4, int slot, int b0, int nb) {
    const float scale = __uint_as_float(g_maxbits[slot]) + 1e-6f;
    for (int i = b0 * 256 + threadIdx.x; i < n4; i += nb * 256) {
        float4 wv = w[i];
        float v0 = snap1(wv.x / scale, scale);
        float v1 = snap1(wv.y / scale, scale);
        float v2 = snap1(wv.z / scale, scale);
        float v3 = snap1(wv.w / scale, scale);
        __nv_bfloat16 h0 = __float2bfloat16(v0), h1 = __float2bfloat16(v1);
        __nv_bfloat16 h2 = __float2bfloat16(v2), h3 = __float2bfloat16(v3);
        uint32_t hp0 = ((uint32_t)__bfloat16_as_ushort(h1) << 16) | __bfloat16_as_ushort(h0);
        uint32_t hp1 = ((uint32_t)__bfloat16_as_ushort(h3) << 16) | __bfloat16_as_ushort(h2);
        uint32_t lp0 = packbf(v0 - __bfloat162float(h0), v1 - __bfloat162float(h1));
        uint32_t lp1 = packbf(v2 - __bfloat162float(h2), v3 - __bfloat162float(h3));
        int r = i >> 8, k = (i & 255) << 2;
        size_t base = (size_t)r * KD2_;
        *(uint2*)(out + base + k)        = make_uint2(hp0, hp1);   // hi
        *(uint2*)(out + base + 1024 + k) = make_uint2(lp0, lp1);   // lo
    }
}

__device__ __forceinline__ void cvt_body(const float4* __restrict__ a,
                                         __nv_bfloat16* __restrict__ out,
                                         int n4, int b0, int nb) {
    for (int i = b0 * 256 + threadIdx.x; i < n4; i += nb * 256) {
        float4 v = a[i];
        __nv_bfloat16 h0 = __float2bfloat16(v.x), h1 = __float2bfloat16(v.y);
        __nv_bfloat16 h2 = __float2bfloat16(v.z), h3 = __float2bfloat16(v.w);
        uint32_t hp0 = ((uint32_t)__bfloat16_as_ushort(h1) << 16) | __bfloat16_as_ushort(h0);
        uint32_t hp1 = ((uint32_t)__bfloat16_as_ushort(h3) << 16) | __bfloat16_as_ushort(h2);
        uint32_t lp0 = packbf(v.x - __bfloat162float(h0), v.y - __bfloat162float(h1));
        uint32_t lp1 = packbf(v.z - __bfloat162float(h2), v.w - __bfloat162float(h3));
        int r = i >> 8, k = (i & 255) << 2;
        size_t base = (size_t)r * KD2_;
        *(uint2*)(out + base + k)        = make_uint2(hp0, hp1);
        *(uint2*)(out + base + 1024 + k) = make_uint2(lp0, lp1);
    }
}

__global__ void __launch_bounds__(256) prep_fused(
    const float4* __restrict__ wa, const float4* __restrict__ wp,
    const float4* __restrict__ x,
    __nv_bfloat16* __restrict__ wa2, __nv_bfloat16* __restrict__ wp2,
    __nv_bfloat16* __restrict__ x2)
{
    const int bx = blockIdx.x;
    if (bx < 512)       snap_body(wa, wa2, (N3C_ * C_) / 4, 0, bx, 512);
    else if (bx < 640)  snap_body(wp, wp2, (C_ * C_) / 4, 1, bx - 512, 128);
    else                cvt_body(x, x2, (M_ * C_) / 4, bx - 640, 512);
}

// ---------------------------------------------------------------------------
// bf16 mma.sync GEMM over [hi|lo] operands, logical K=1024, BK=32.
// Per chunk: load Ah,Al,Bh,Bl tiles (cp.async 2-stage), 3 MMA passes from
// register-resident fragments (AhBh + AhBl + AlBh). 128x128 tile, 8 warps.
// ---------------------------------------------------------------------------
#define GP_    80                    // smem row stride (bytes) per 32-col tile
#define GT_    (128 * GP_)           // 10240 per tile
#define GSTAGE (4 * GT_)             // 40960 per stage (Ah,Al,Bh,Bl)
#define GEMM_SMEM (2 * GSTAGE)       // 81920
#define GNIT_  32                    // 1024 / 32

template <int SPLIT>
__global__ void __launch_bounds__(256, 2)
gemm_mma(const __nv_bfloat16* __restrict__ A2, const __nv_bfloat16* __restrict__ B2,
         const float* __restrict__ bias, float* __restrict__ Cf,
         __nv_bfloat16* __restrict__ Chi, __nv_bfloat16* __restrict__ Clo, int Nd)
{
    extern __shared__ char gsm[];
    const uint32_t sbase = smem_u32(gsm);
    const int tid  = threadIdx.x;
    const int lane = tid & 31;
    const int wid  = tid >> 5;
    const int wm   = wid >> 2;
    const int wn   = wid & 3;
    const int m0   = blockIdx.y * 128;
    const int n0   = blockIdx.x * 128;

    // loader: 2 threads/row; each thread covers 2 x 16B chunks per tile
    const int lr  = tid >> 1;
    const int lc2 = (tid & 1) * 2;              // chunk 0-1 or 2-3
    const __nv_bfloat16* gA = A2 + (size_t)(m0 + lr) * KD2_;
    const __nv_bfloat16* gB = B2 + (size_t)(n0 + lr) * KD2_;
    const uint32_t soff = (uint32_t)(lr * GP_ + lc2 * 16);

    const uint32_t aoff = (uint32_t)((wm * 64 + (lane & 15)) * GP_ + (lane >> 4) * 16);
    const uint32_t boff = (uint32_t)((wn * 32 + (lane & 7) + ((lane >> 4) & 1) * 8) * GP_
                                     + ((lane >> 3) & 1) * 16);

    float acc[4][4][4] = {};

    auto issue = [&](int it, int s) {
        const uint32_t sb = sbase + s * GSTAGE + soff;
        const int k0 = it * 32 + lc2 * 8;
        cp16(sb,                  gA + k0);              // Ah
        cp16(sb + 16,             gA + k0 + 8);
        cp16(sb + GT_,            gA + 1024 + k0);       // Al
        cp16(sb + GT_ + 16,       gA + 1024 + k0 + 8);
        cp16(sb + 2 * GT_,        gB + k0);              // Bh
        cp16(sb + 2 * GT_ + 16,   gB + k0 + 8);
        cp16(sb + 3 * GT_,        gB + 1024 + k0);       // Bl
        cp16(sb + 3 * GT_ + 16,   gB + 1024 + k0 + 8);
        CP_COMMIT();
    };

    issue(0, 0);
    issue(1, 1);

    for (int it = 0; it < GNIT_; ++it) {
        if (it + 1 < GNIT_) { CP_WAIT1(); } else { CP_WAIT0(); }
        __syncthreads();

        const uint32_t sb = sbase + (it & 1) * GSTAGE;
        #pragma unroll
        for (int ks = 0; ks < 2; ++ks) {
            const uint32_t kso = (uint32_t)(ks * 32);
            uint32_t bh0[4], bh1[4], bl0[4], bl1[4], af[4][4];
            ldsm_x4(bh0, sb + 2 * GT_ + boff + kso);
            ldsm_x4(bh1, sb + 2 * GT_ + boff + 16 * GP_ + kso);
            #pragma unroll
            for (int mt = 0; mt < 4; ++mt)
                ldsm_x4(af[mt], sb + aoff + mt * (16 * GP_) + kso);   // Ah
            #pragma unroll
            for (int mt = 0; mt < 4; ++mt) {
                mma_bf16(acc[mt][0], af[mt], bh0[0], bh0[1]);
                mma_bf16(acc[mt][1], af[mt], bh0[2], bh0[3]);
                mma_bf16(acc[mt][2], af[mt], bh1[0], bh1[1]);
                mma_bf16(acc[mt][3], af[mt], bh1[2], bh1[3]);
            }
            ldsm_x4(bl0, sb + 3 * GT_ + boff + kso);
            ldsm_x4(bl1, sb + 3 * GT_ + boff + 16 * GP_ + kso);
            #pragma unroll
            for (int mt = 0; mt < 4; ++mt) {
                mma_bf16(acc[mt][0], af[mt], bl0[0], bl0[1]);
                mma_bf16(acc[mt][1], af[mt], bl0[2], bl0[3]);
                mma_bf16(acc[mt][2], af[mt], bl1[0], bl1[1]);
                mma_bf16(acc[mt][3], af[mt], bl1[2], bl1[3]);
            }
            #pragma unroll
            for (int mt = 0; mt < 4; ++mt)
                ldsm_x4(af[mt], sb + GT_ + aoff + mt * (16 * GP_) + kso);  // Al
            #pragma unroll
            for (int mt = 0; mt < 4; ++mt) {
                mma_bf16(acc[mt][0], af[mt], bh0[0], bh0[1]);
                mma_bf16(acc[mt][1], af[mt], bh0[2], bh0[3]);
                mma_bf16(acc[mt][2], af[mt], bh1[0], bh1[1]);
                mma_bf16(acc[mt][3], af[mt], bh1[2], bh1[3]);
            }
        }

        if (it + 2 < GNIT_) {
            __syncthreads();            // all reads of buf (it&1) done
            issue(it + 2, it & 1);
        }
    }

    #pragma unroll
    for (int nt = 0; nt < 4; ++nt) {
        const int col = n0 + wn * 32 + nt * 8 + (lane & 3) * 2;
        const float bv0 = bias[col];
        const float bv1 = bias[col + 1];
        #pragma unroll
        for (int mt = 0; mt < 4; ++mt) {
            const int row = m0 + wm * 64 + mt * 16 + (lane >> 2);
            float v0 = acc[mt][nt][0] + bv0, v1 = acc[mt][nt][1] + bv1;
            float v2 = acc[mt][nt][2] + bv0, v3 = acc[mt][nt][3] + bv1;
            if (SPLIT) {
                __nv_bfloat16 h0 = __float2bfloat16(v0), h1 = __float2bfloat16(v1);
                __nv_bfloat16 h2 = __float2bfloat16(v2), h3 = __float2bfloat16(v3);
                uint32_t hp0 = ((uint32_t)__bfloat16_as_ushort(h1) << 16) | __bfloat16_as_ushort(h0);
                uint32_t hp1 = ((uint32_t)__bfloat16_as_ushort(h3) << 16) | __bfloat16_as_ushort(h2);
                uint32_t lp0 = packbf(v0 - __bfloat162float(h0), v1 - __bfloat162float(h1));
                uint32_t lp1 = packbf(v2 - __bfloat162float(h2), v3 - __bfloat162float(h3));
                *(uint32_t*)(Chi + (size_t)row * Nd + col)       = hp0;
                *(uint32_t*)(Chi + (size_t)(row + 8) * Nd + col) = hp1;
                *(uint32_t*)(Clo + (size_t)row * Nd + col)       = lp0;
                *(uint32_t*)(Clo + (size_t)(row + 8) * Nd + col) = lp1;
            } else {
                float2 o0, o1;
                o0.x = v0; o0.y = v1;
                o1.x = v2; o1.y = v3;
                *(float2*)&Cf[(size_t)row * Nd + col]       = o0;
                *(float2*)&Cf[(size_t)(row + 8) * Nd + col] = o1;
            }
        }
    }
}

// ---------------------------------------------------------------------------
// Tensor-core causal flash attention (proven R10 body): bf16 split HMMA,
// 128-q tile, 8 warps x 16 rows, 64-key tiles double-buffered.
// Epilogue writes y in [hi|lo] layout (stride 2048) for the proj GEMM.
// ---------------------------------------------------------------------------
#define SQH_  0
#define SQL_  (128 * 144)            // 18432
#define SKV0_ (2 * 128 * 144)        // 36864
#define KVBUF_ (4 * 64 * 144)        // 36864 (KH, KL, VH, VL)
#define ATTN_SMEM (SKV0_ + 2 * KVBUF_)   // 110592

__global__ void __launch_bounds__(256, 1)
attn_mma(const __nv_bfloat16* __restrict__ qh_g, const __nv_bfloat16* __restrict__ ql_g,
         __nv_bfloat16* __restrict__ y2)
{
    extern __shared__ char sm[];
    const uint32_t base = smem_u32(sm);
    const int tid  = threadIdx.x;
    const int lane = tid & 31;
    const int wid  = tid >> 5;
    const int qt   = (int)gridDim.x - 1 - (int)blockIdx.x;   // long blocks first
    const int bh   = blockIdx.y;
    const int bb   = bh >> 4;
    const int h    = bh & 15;
    const int qbase = qt * 128;

    // ---- load Q tile hi/lo into smem ----
    {
        const int r  = tid >> 1;
        const int c0 = (tid & 1) * 4;
        const size_t ro = ((size_t)(bb * T_ + qbase + r)) * 3072 + h * 64;
        const uint4* sh = (const uint4*)(qh_g + ro) + c0;
        const uint4* sl = (const uint4*)(ql_g + ro) + c0;
        #pragma unroll
        for (int c = 0; c < 4; ++c) {
            *(uint4*)(sm + SQH_ + r * 144 + (c0 + c) * 16) = sh[c];
            *(uint4*)(sm + SQL_ + r * 144 + (c0 + c) * 16) = sl[c];
        }
    }
    __syncthreads();

    // ---- Q fragments resident in registers for all k tiles ----
    const uint32_t aoff = (uint32_t)((wid * 16 + (lane & 15)) * 144 + (lane >> 4) * 16);
    uint32_t qhf[4][4], qlf[4][4];
    #pragma unroll
    for (int kc = 0; kc < 4; ++kc) {
        ldsm_x4(qhf[kc], base + SQH_ + aoff + kc * 32);
        ldsm_x4(qlf[kc], base + SQL_ + aoff + kc * 32);
    }

    // KV loader mapping: 64 rows x 8 uint4, 256 threads -> 2 uint4/thread/subtile
    const int kr  = tid >> 2;
    const int kc4 = (tid & 3) * 2;
    const int ckq = (1024 + h * 64) >> 3;
    const int cvq = (2048 + h * 64) >> 3;

    float mrow0 = -INFINITY, mrow1 = -INFINITY, lr0 = 0.0f, lr1 = 0.0f;
    float accO[8][4] = {};

    const int nkt = 2 * qt + 2;
    const int qwbase = qbase + wid * 16;
    const int r0g = qwbase + (lane >> 2);
    const float sc = 0.125f;   // 1/sqrt(64)

    uint4 stage[8];
    // load + store tile 0
    {
        const size_t ro = ((size_t)(bb * T_ + kr)) * 3072;
        const uint4* ph = (const uint4*)(qh_g + ro);
        const uint4* pl = (const uint4*)(ql_g + ro);
        stage[0] = ph[ckq + kc4]; stage[1] = ph[ckq + kc4 + 1];
        stage[2] = pl[ckq + kc4]; stage[3] = pl[ckq + kc4 + 1];
        stage[4] = ph[cvq + kc4]; stage[5] = ph[cvq + kc4 + 1];
        stage[6] = pl[cvq + kc4]; stage[7] = pl[cvq + kc4 + 1];
        char* d = sm + SKV0_ + kr * 144 + kc4 * 16;
        *(uint4*)(d)             = stage[0]; *(uint4*)(d + 16)         = stage[1];
        *(uint4*)(d + 9216)      = stage[2]; *(uint4*)(d + 9216 + 16)  = stage[3];
        *(uint4*)(d + 18432)     = stage[4]; *(uint4*)(d + 18432 + 16) = stage[5];
        *(uint4*)(d + 27648)     = stage[6]; *(uint4*)(d + 27648 + 16) = stage[7];
    }
    __syncthreads();

    for (int j = 0; j < nkt; ++j) {
        const int buf = j & 1;
        const int kbase = j * 64;

        if (j + 1 < nkt) {   // prefetch next tile into registers
            const size_t ro = ((size_t)(bb * T_ + (j + 1) * 64 + kr)) * 3072;
            const uint4* ph = (const uint4*)(qh_g + ro);
            const uint4* pl = (const uint4*)(ql_g + ro);
            stage[0] = ph[ckq + kc4]; stage[1] = ph[ckq + kc4 + 1];
            stage[2] = pl[ckq + kc4]; stage[3] = pl[ckq + kc4 + 1];
            stage[4] = ph[cvq + kc4]; stage[5] = ph[cvq + kc4 + 1];
            stage[6] = pl[cvq + kc4]; stage[7] = pl[cvq + kc4 + 1];
        }

        if (kbase <= qwbase + 15) {   // per-warp causal skip
            const uint32_t kvb = base + SKV0_ + buf * KVBUF_;

            // ---- S = Q K^T (3-term split) ----
            float sa[8][4];
            #pragma unroll
            for (int nt = 0; nt < 8; ++nt)
                #pragma unroll
                for (int i = 0; i < 4; ++i) sa[nt][i] = 0.0f;

            #pragma unroll
            for (int kc = 0; kc < 4; ++kc) {
                #pragma unroll
                for (int p = 0; p < 4; ++p) {
                    const uint32_t bo = (uint32_t)((p * 16 + (lane & 7) + ((lane >> 4) & 1) * 8) * 144
                                                   + ((lane >> 3) & 1) * 16 + kc * 32);
                    uint32_t kh[4], kl[4];
                    ldsm_x4(kh, kvb + bo);
                    ldsm_x4(kl, kvb + 9216 + bo);
                    mma_bf16(sa[2 * p],     qhf[kc], kh[0], kh[1]);
                    mma_bf16(sa[2 * p + 1], qhf[kc], kh[2], kh[3]);
                    mma_bf16(sa[2 * p],     qlf[kc], kh[0], kh[1]);
                    mma_bf16(sa[2 * p + 1], qlf[kc], kh[2], kh[3]);
                    mma_bf16(sa[2 * p],     qhf[kc], kl[0], kl[1]);
                    mma_bf16(sa[2 * p + 1], qhf[kc], kl[2], kl[3]);
                }
            }

            // ---- online softmax ----
            const bool diag = (kbase + 63 > qwbase);
            float mx0 = -INFINITY, mx1 = -INFINITY;
            #pragma unroll
            for (int nt = 0; nt < 8; ++nt) {
                const int col = kbase + nt * 8 + (lane & 3) * 2;
                float s0 = sa[nt][0] * sc, s1 = sa[nt][1] * sc;
                float s2 = sa[nt][2] * sc, s3 = sa[nt][3] * sc;
                if (diag) {
                    if (col     > r0g)     s0 = -INFINITY;
                    if (col + 1 > r0g)     s1 = -INFINITY;
                    if (col     > r0g + 8) s2 = -INFINITY;
                    if (col + 1 > r0g + 8) s3 = -INFINITY;
                }
                sa[nt][0] = s0; sa[nt][1] = s1; sa[nt][2] = s2; sa[nt][3] = s3;
                mx0 = fmaxf(mx0, fmaxf(s0, s1));
                mx1 = fmaxf(mx1, fmaxf(s2, s3));
            }
            mx0 = fmaxf(mx0, __shfl_xor_sync(0xffffffffu, mx0, 1));
            mx0 = fmaxf(mx0, __shfl_xor_sync(0xffffffffu, mx0, 2));
            mx1 = fmaxf(mx1, __shfl_xor_sync(0xffffffffu, mx1, 1));
            mx1 = fmaxf(mx1, __shfl_xor_sync(0xffffffffu, mx1, 2));

            const float mn0 = fmaxf(mrow0, mx0), mn1 = fmaxf(mrow1, mx1);
            const float f0 = __expf(mrow0 - mn0), f1 = __expf(mrow1 - mn1);
            mrow0 = mn0; mrow1 = mn1;

            float sum0 = 0.0f, sum1 = 0.0f;
            #pragma unroll
            for (int nt = 0; nt < 8; ++nt) {
                float p0 = __expf(sa[nt][0] - mn0);
                float p1 = __expf(sa[nt][1] - mn0);
                float p2 = __expf(sa[nt][2] - mn1);
                float p3 = __expf(sa[nt][3] - mn1);
                sa[nt][0] = p0; sa[nt][1] = p1; sa[nt][2] = p2; sa[nt][3] = p3;
                sum0 += p0 + p1;
                sum1 += p2 + p3;
            }
            sum0 += __shfl_xor_sync(0xffffffffu, sum0, 1);
            sum0 += __shfl_xor_sync(0xffffffffu, sum0, 2);
            sum1 += __shfl_xor_sync(0xffffffffu, sum1, 1);
            sum1 += __shfl_xor_sync(0xffffffffu, sum1, 2);
            lr0 = lr0 * f0 + sum0;
            lr1 = lr1 * f1 + sum1;
            #pragma unroll
            for (int nt = 0; nt < 8; ++nt) {
                accO[nt][0] *= f0; accO[nt][1] *= f0;
                accO[nt][2] *= f1; accO[nt][3] *= f1;
            }

            // ---- P -> A-fragments (register repack, exact hi/lo split) ----
            uint32_t phf[4][4], plf[4][4];
            #pragma unroll
            for (int kc = 0; kc < 4; ++kc) {
                #pragma unroll
                for (int half = 0; half < 2; ++half) {
                    const int nt = 2 * kc + half;
                    float v0 = sa[nt][0], v1 = sa[nt][1];
                    float v2 = sa[nt][2], v3 = sa[nt][3];
                    __nv_bfloat16 h0 = __float2bfloat16(v0), h1 = __float2bfloat16(v1);
                    __nv_bfloat16 h2 = __float2bfloat16(v2), h3 = __float2bfloat16(v3);
                    phf[kc][half * 2 + 0] = ((uint32_t)__bfloat16_as_ushort(h1) << 16)
                                            | __bfloat16_as_ushort(h0);
                    phf[kc][half * 2 + 1] = ((uint32_t)__bfloat16_as_ushort(h3) << 16)
                                            | __bfloat16_as_ushort(h2);
                    plf[kc][half * 2 + 0] = packbf(v0 - __bfloat162float(h0),
                                                   v1 - __bfloat162float(h1));
                    plf[kc][half * 2 + 1] = packbf(v2 - __bfloat162float(h2),
                                                   v3 - __bfloat162float(h3));
                }
            }

            // ---- accO += P V (3-term split, ldmatrix.trans on V) ----
            const uint32_t voff = (uint32_t)((lane & 15) * 144 + (lane >> 4) * 16);
            #pragma unroll
            for (int kc = 0; kc < 4; ++kc) {
                #pragma unroll
                for (int np = 0; np < 4; ++np) {
                    uint32_t vh[4], vl[4];
                    const uint32_t va = kvb + voff + kc * (16 * 144) + np * 32;
                    ldsm_x4_t(vh, va + 18432);
                    ldsm_x4_t(vl, va + 27648);
                    mma_bf16(accO[2 * np],     phf[kc], vh[0], vh[1]);
                    mma_bf16(accO[2 * np + 1], phf[kc], vh[2], vh[3]);
                    mma_bf16(accO[2 * np],     plf[kc], vh[0], vh[1]);
                    mma_bf16(accO[2 * np + 1], plf[kc], vh[2], vh[3]);
                    mma_bf16(accO[2 * np],     phf[kc], vl[0], vl[1]);
                    mma_bf16(accO[2 * np + 1], phf[kc], vl[2], vl[3]);
                }
            }
        }

        if (j + 1 < nkt) {   // store prefetched tile into the other buffer
            char* d = sm + SKV0_ + (1 - buf) * KVBUF_ + kr * 144 + kc4 * 16;
            *(uint4*)(d)             = stage[0]; *(uint4*)(d + 16)         = stage[1];
            *(uint4*)(d + 9216)      = stage[2]; *(uint4*)(d + 9216 + 16)  = stage[3];
            *(uint4*)(d + 18432)     = stage[4]; *(uint4*)(d + 18432 + 16) = stage[5];
            *(uint4*)(d + 27648)     = stage[6]; *(uint4*)(d + 27648 + 16) = stage[7];
        }
        __syncthreads();
    }

    // ---- epilogue: normalize, write [hi|lo] (stride 2048) to y2 ----
    const float inv0 = 1.0f / lr0, inv1 = 1.0f / lr1;
    const size_t row0 = (size_t)(bb * T_ + qwbase + (lane >> 2));
    const int colb = h * 64 + (lane & 3) * 2;
    #pragma unroll
    for (int nt = 0; nt < 8; ++nt) {
        const int col = colb + nt * 8;
        float v0 = accO[nt][0] * inv0, v1 = accO[nt][1] * inv0;
        float v2 = accO[nt][2] * inv1, v3 = accO[nt][3] * inv1;
        __nv_bfloat16 h0 = __float2bfloat16(v0), h1 = __float2bfloat16(v1);
        __nv_bfloat16 h2 = __float2bfloat16(v2), h3 = __float2bfloat16(v3);
        uint32_t hp0 = ((uint32_t)__bfloat16_as_ushort(h1) << 16) | __bfloat16_as_ushort(h0);
        uint32_t hp1 = ((uint32_t)__bfloat16_as_ushort(h3) << 16) | __bfloat16_as_ushort(h2);
        uint32_t lp0 = packbf(v0 - __bfloat162float(h0), v1 - __bfloat162float(h1));
        uint32_t lp1 = packbf(v2 - __bfloat162float(h2), v3 - __bfloat162float(h3));
        *(uint32_t*)(y2 + row0 * KD2_ + col)              = hp0;
        *(uint32_t*)(y2 + row0 * KD2_ + 1024 + col)       = lp0;
        *(uint32_t*)(y2 + (row0 + 8) * KD2_ + col)        = hp1;
        *(uint32_t*)(y2 + (row0 + 8) * KD2_ + 1024 + col) = lp1;
    }
}

// ---------------------------------------------------------------------------
// Launch
// ---------------------------------------------------------------------------
extern "C" void kernel_launch(void* const* d_in, const int* in_sizes, int n_in,
                              void* d_out, int out_size)
{
    (void)in_sizes; (void)n_in; (void)out_size;
    const float* x      = (const float*)d_in[0];
    const float* w_attn = (const float*)d_in[1];
    const float* b_attn = (const float*)d_in[2];
    const float* w_proj = (const float*)d_in[3];
    const float* b_proj = (const float*)d_in[4];
    float* out = (float*)d_out;

    __nv_bfloat16 *x2, *y2, *wa2, *wp2, *qkvh, *qkvl;
    cudaGetSymbolAddress((void**)&x2,   g_x2);
    cudaGetSymbolAddress((void**)&y2,   g_y2);
    cudaGetSymbolAddress((void**)&wa2,  g_wa2);
    cudaGetSymbolAddress((void**)&wp2,  g_wp2);
    cudaGetSymbolAddress((void**)&qkvh, g_qkvh);
    cudaGetSymbolAddress((void**)&qkvl, g_qkvl);

    cudaFuncSetAttribute(attn_mma, cudaFuncAttributeMaxDynamicSharedMemorySize,
                         ATTN_SMEM);
    cudaFuncSetAttribute(gemm_mma<1>, cudaFuncAttributeMaxDynamicSharedMemorySize,
                         GEMM_SMEM);
    cudaFuncSetAttribute(gemm_mma<0>, cudaFuncAttributeMaxDynamicSharedMemorySize,
                         GEMM_SMEM);

    // 1) prologue: scales, snap -> [hi|lo], x -> [hi|lo]
    zero_scales_kernel<<<1, 1>>>();
    maxabs_fused<<<512, 256>>>((const float4*)w_attn, (const float4*)w_proj);
    prep_fused<<<1152, 256>>>((const float4*)w_attn, (const float4*)w_proj,
                              (const float4*)x, wa2, wp2, x2);

    // 2) qkv = x @ snap(w_attn)^T + b_attn  -> bf16 hi/lo
    gemm_mma<1><<<dim3(N3C_ / 128, M_ / 128), 256, GEMM_SMEM>>>(
        x2, wa2, b_attn, nullptr, qkvh, qkvl, N3C_);

    // 3) tensor-core causal flash attention -> y2 ([hi|lo])
    attn_mma<<<dim3(T_ / 128, B_ * H_), 256, ATTN_SMEM>>>(qkvh, qkvl, y2);

    // 4) out = y @ snap(w_proj)^T + b_proj  (fp32 out)
    gemm_mma<0><<<dim3(C_ / 128, M_ / 128), 256, GEMM_SMEM>>>(
        y2, wp2, b_proj, out, nullptr, nullptr, C_);
}

// round 13
// speedup vs baseline: 1.5448x; 1.3430x over previous
#include <cuda_runtime.h>
#include <cuda_fp16.h>
#include <math.h>
#include <stdint.h>

// Problem constants
#define B_   2
#define T_   2048
#define C_   1024
#define H_   16
#define M_   (B_ * T_)      // 4096
#define N3C_ (3 * C_)       // 3072
#define KD1_ 1024           // single-fp16 activation K width
#define KD2_ 2048           // [hi|lo] fp16 weight K width

// ---------------------------------------------------------------------------
// Helpers
// ---------------------------------------------------------------------------
__device__ __forceinline__ uint32_t smem_u32(const void* p) {
    uint32_t a;
    asm("{ .reg .u64 t; cvta.to.shared.u64 t, %1; cvt.u32.u64 %0, t; }"
        : "=r"(a) : "l"(p));
    return a;
}

__device__ __forceinline__ void ldsm_x4(uint32_t (&r)[4], uint32_t addr) {
    asm volatile("ldmatrix.sync.aligned.m8n8.x4.shared.b16 {%0,%1,%2,%3}, [%4];"
                 : "=r"(r[0]), "=r"(r[1]), "=r"(r[2]), "=r"(r[3]) : "r"(addr));
}

__device__ __forceinline__ void ldsm_x4_t(uint32_t (&r)[4], uint32_t addr) {
    asm volatile("ldmatrix.sync.aligned.m8n8.x4.trans.shared.b16 {%0,%1,%2,%3}, [%4];"
                 : "=r"(r[0]), "=r"(r[1]), "=r"(r[2]), "=r"(r[3]) : "r"(addr));
}

__device__ __forceinline__ void mma_f16(float (&c)[4], const uint32_t (&a)[4],
                                        uint32_t b0, uint32_t b1) {
    asm volatile(
        "mma.sync.aligned.m16n8k16.row.col.f32.f16.f16.f32 "
        "{%0,%1,%2,%3}, {%4,%5,%6,%7}, {%8,%9}, {%0,%1,%2,%3};"
        : "+f"(c[0]), "+f"(c[1]), "+f"(c[2]), "+f"(c[3])
        : "r"(a[0]), "r"(a[1]), "r"(a[2]), "r"(a[3]), "r"(b0), "r"(b1));
}

// pack two f32 -> f16x2, lo in lower half
__device__ __forceinline__ uint32_t packh(float lo, float hi) {
    uint32_t u;
    asm("cvt.rn.f16x2.f32 %0, %1, %2;" : "=r"(u) : "f"(hi), "f"(lo));
    return u;
}

__device__ __forceinline__ void cp16(uint32_t dst, const void* src) {
    asm volatile("cp.async.cg.shared.global [%0], [%1], 16;"
                 :: "r"(dst), "l"(src) : "memory");
}
#define CP_COMMIT() asm volatile("cp.async.commit_group;" ::: "memory")
#define CP_WAIT1()  asm volatile("cp.async.wait_group 1;" ::: "memory")
#define CP_WAIT0()  asm volatile("cp.async.wait_group 0;" ::: "memory")

// ---------------------------------------------------------------------------
// Scratch (device globals)
// ---------------------------------------------------------------------------
__device__ __half g_x2[(size_t)M_ * KD1_];    // x  (single fp16)
__device__ __half g_y2[(size_t)M_ * KD1_];    // attn out (single fp16)
__device__ __half g_wa2[(size_t)N3C_ * KD2_]; // snap(w_attn) [hi|lo]
__device__ __half g_wp2[(size_t)C_ * KD2_];   // snap(w_proj) [hi|lo]
__device__ __half g_qkvh[(size_t)M_ * N3C_];  // qkv hi
__device__ __half g_qkvl[(size_t)M_ * N3C_];  // qkv lo
__device__ unsigned int g_maxbits[2];

// ---------------------------------------------------------------------------
// Prologue (exact argmin + exact division)
// ---------------------------------------------------------------------------
__global__ void zero_scales_kernel() { g_maxbits[0] = 0u; g_maxbits[1] = 0u; }

__device__ __forceinline__ void maxabs_body(const float4* __restrict__ w,
                                            int n4, int slot, int b0, int nb) {
    float m = 0.0f;
    for (int i = b0 * 256 + threadIdx.x; i < n4; i += nb * 256) {
        float4 v = w[i];
        m = fmaxf(m, fmaxf(fmaxf(fabsf(v.x), fabsf(v.y)),
                           fmaxf(fabsf(v.z), fabsf(v.w))));
    }
    #pragma unroll
    for (int o = 16; o > 0; o >>= 1)
        m = fmaxf(m, __shfl_xor_sync(0xffffffffu, m, o));
    __shared__ float sm[8];
    int lane = threadIdx.x & 31, wd = threadIdx.x >> 5;
    if (lane == 0) sm[wd] = m;
    __syncthreads();
    if (threadIdx.x < 8) {
        m = sm[threadIdx.x];
        #pragma unroll
        for (int o = 4; o > 0; o >>= 1)
            m = fmaxf(m, __shfl_xor_sync(0xffu, m, o));
        if (threadIdx.x == 0)
            atomicMax(&g_maxbits[slot], __float_as_uint(m));
    }
}

__global__ void __launch_bounds__(256) maxabs_fused(const float4* __restrict__ wa,
                                                    const float4* __restrict__ wp) {
    const int bx = blockIdx.x;
    if (bx < 384) maxabs_body(wa, (N3C_ * C_) / 4, 0, bx, 384);
    else          maxabs_body(wp, (C_ * C_) / 4, 1, bx - 384, 128);
}

// exact argmin over the 16-entry LUT (reference order, strict < tie-break)
__device__ __forceinline__ float snap1(float wn, float scale) {
    const float L1 = 1.0f,      L3 = 0.5f,      L5 = 0.333333f, L7 = 0.2f,
                L9 = 0.142857f, L11 = 0.090909f, L13 = 0.076923f;
    float bd = fabsf(wn);       // LUT[0] = 0
    float bv = 0.0f;
    #define TRY_(val) { float d_ = fabsf(wn - (val)); if (d_ < bd) { bd = d_; bv = (val); } }
    TRY_(L1)  TRY_(-L1)  TRY_(L3)  TRY_(-L3)  TRY_(L5)  TRY_(-L5)  TRY_(L7)
    TRY_(-L7) TRY_(L9)   TRY_(-L9) TRY_(L11)  TRY_(-L11) TRY_(L13) TRY_(-L13)
    #undef TRY_
    return bv * scale;
}

__device__ __forceinline__ void snap_body(const float4* __restrict__ w,
                                          __half* __restrict__ out,
                                          int n4, int slot, int b0, int nb) {
    const float scale = __uint_as_float(g_maxbits[slot]) + 1e-6f;
    for (int i = b0 * 256 + threadIdx.x; i < n4; i += nb * 256) {
        float4 wv = w[i];
        float v0 = snap1(wv.x / scale, scale);
        float v1 = snap1(wv.y / scale, scale);
        float v2 = snap1(wv.z / scale, scale);
        float v3 = snap1(wv.w / scale, scale);
        __half h0 = __float2half_rn(v0), h1 = __float2half_rn(v1);
        __half h2 = __float2half_rn(v2), h3 = __float2half_rn(v3);
        uint32_t hp0 = ((uint32_t)__half_as_ushort(h1) << 16) | __half_as_ushort(h0);
        uint32_t hp1 = ((uint32_t)__half_as_ushort(h3) << 16) | __half_as_ushort(h2);
        uint32_t lp0 = packh(v0 - __half2float(h0), v1 - __half2float(h1));
        uint32_t lp1 = packh(v2 - __half2float(h2), v3 - __half2float(h3));
        int r = i >> 8, k = (i & 255) << 2;
        size_t base = (size_t)r * KD2_;
        *(uint2*)(out + base + k)        = make_uint2(hp0, hp1);   // hi
        *(uint2*)(out + base + 1024 + k) = make_uint2(lp0, lp1);   // lo
    }
}

__device__ __forceinline__ void cvt_body(const float4* __restrict__ a,
                                         __half* __restrict__ out,
                                         int n4, int b0, int nb) {
    for (int i = b0 * 256 + threadIdx.x; i < n4; i += nb * 256) {
        float4 v = a[i];
        uint32_t hp0 = packh(v.x, v.y), hp1 = packh(v.z, v.w);
        int r = i >> 8, k = (i & 255) << 2;
        *(uint2*)(out + (size_t)r * KD1_ + k) = make_uint2(hp0, hp1);
    }
}

__global__ void __launch_bounds__(256) prep_fused(
    const float4* __restrict__ wa, const float4* __restrict__ wp,
    const float4* __restrict__ x,
    __half* __restrict__ wa2, __half* __restrict__ wp2,
    __half* __restrict__ x2)
{
    const int bx = blockIdx.x;
    if (bx < 512)       snap_body(wa, wa2, (N3C_ * C_) / 4, 0, bx, 512);
    else if (bx < 640)  snap_body(wp, wp2, (C_ * C_) / 4, 1, bx - 512, 128);
    else                cvt_body(x, x2, (M_ * C_) / 4, bx - 640, 384);
}

// ---------------------------------------------------------------------------
// fp16 mma.sync GEMM: A single-fp16 (K=1024), B [hi|lo] (K'=2048).
// 2 MMA passes per k16: Ah*Bh + Ah*Bl. 128x128 tile, BK=32, cp.async 2-stage.
// ---------------------------------------------------------------------------
#define GP_    80                    // smem row stride (bytes) per 32-col tile
#define GT_    (128 * GP_)           // 10240 per tile
#define GSTAGE (3 * GT_)             // 30720 per stage (Ah,Bh,Bl)
#define GEMM_SMEM (2 * GSTAGE)       // 61440
#define GNIT_  32                    // 1024 / 32

template <int SPLIT>
__global__ void __launch_bounds__(256, 2)
gemm_mma(const __half* __restrict__ A2, const __half* __restrict__ B2,
         const float* __restrict__ bias, float* __restrict__ Cf,
         __half* __restrict__ Chi, __half* __restrict__ Clo, int Nd)
{
    extern __shared__ char gsm[];
    const uint32_t sbase = smem_u32(gsm);
    const int tid  = threadIdx.x;
    const int lane = tid & 31;
    const int wid  = tid >> 5;
    const int wm   = wid >> 2;
    const int wn   = wid & 3;
    const int m0   = blockIdx.y * 128;
    const int n0   = blockIdx.x * 128;

    // loader: 2 threads/row; each thread covers 2 x 16B chunks per tile
    const int lr  = tid >> 1;
    const int lc2 = (tid & 1) * 2;              // chunk 0-1 or 2-3
    const __half* gA = A2 + (size_t)(m0 + lr) * KD1_;
    const __half* gB = B2 + (size_t)(n0 + lr) * KD2_;
    const uint32_t soff = (uint32_t)(lr * GP_ + lc2 * 16);

    const uint32_t aoff = (uint32_t)((wm * 64 + (lane & 15)) * GP_ + (lane >> 4) * 16);
    const uint32_t boff = (uint32_t)((wn * 32 + (lane & 7) + ((lane >> 4) & 1) * 8) * GP_
                                     + ((lane >> 3) & 1) * 16);

    float acc[4][4][4] = {};

    auto issue = [&](int it, int s) {
        const uint32_t sb = sbase + s * GSTAGE + soff;
        const int k0 = it * 32 + lc2 * 8;
        cp16(sb,                gA + k0);              // Ah
        cp16(sb + 16,           gA + k0 + 8);
        cp16(sb + GT_,          gB + k0);              // Bh
        cp16(sb + GT_ + 16,     gB + k0 + 8);
        cp16(sb + 2 * GT_,      gB + 1024 + k0);       // Bl
        cp16(sb + 2 * GT_ + 16, gB + 1024 + k0 + 8);
        CP_COMMIT();
    };

    issue(0, 0);
    issue(1, 1);

    for (int it = 0; it < GNIT_; ++it) {
        if (it + 1 < GNIT_) { CP_WAIT1(); } else { CP_WAIT0(); }
        __syncthreads();

        const uint32_t sb = sbase + (it & 1) * GSTAGE;
        #pragma unroll
        for (int ks = 0; ks < 2; ++ks) {
            const uint32_t kso = (uint32_t)(ks * 32);
            uint32_t bh0[4], bh1[4], bl0[4], bl1[4], af[4][4];
            ldsm_x4(bh0, sb + GT_ + boff + kso);
            ldsm_x4(bh1, sb + GT_ + boff + 16 * GP_ + kso);
            #pragma unroll
            for (int mt = 0; mt < 4; ++mt)
                ldsm_x4(af[mt], sb + aoff + mt * (16 * GP_) + kso);   // Ah
            #pragma unroll
            for (int mt = 0; mt < 4; ++mt) {
                mma_f16(acc[mt][0], af[mt], bh0[0], bh0[1]);
                mma_f16(acc[mt][1], af[mt], bh0[2], bh0[3]);
                mma_f16(acc[mt][2], af[mt], bh1[0], bh1[1]);
                mma_f16(acc[mt][3], af[mt], bh1[2], bh1[3]);
            }
            ldsm_x4(bl0, sb + 2 * GT_ + boff + kso);
            ldsm_x4(bl1, sb + 2 * GT_ + boff + 16 * GP_ + kso);
            #pragma unroll
            for (int mt = 0; mt < 4; ++mt) {
                mma_f16(acc[mt][0], af[mt], bl0[0], bl0[1]);
                mma_f16(acc[mt][1], af[mt], bl0[2], bl0[3]);
                mma_f16(acc[mt][2], af[mt], bl1[0], bl1[1]);
                mma_f16(acc[mt][3], af[mt], bl1[2], bl1[3]);
            }
        }

        if (it + 2 < GNIT_) {
            __syncthreads();            // all reads of buf (it&1) done
            issue(it + 2, it & 1);
        }
    }

    #pragma unroll
    for (int nt = 0; nt < 4; ++nt) {
        const int col = n0 + wn * 32 + nt * 8 + (lane & 3) * 2;
        const float bv0 = bias[col];
        const float bv1 = bias[col + 1];
        #pragma unroll
        for (int mt = 0; mt < 4; ++mt) {
            const int row = m0 + wm * 64 + mt * 16 + (lane >> 2);
            float v0 = acc[mt][nt][0] + bv0, v1 = acc[mt][nt][1] + bv1;
            float v2 = acc[mt][nt][2] + bv0, v3 = acc[mt][nt][3] + bv1;
            if (SPLIT) {
                __half h0 = __float2half_rn(v0), h1 = __float2half_rn(v1);
                __half h2 = __float2half_rn(v2), h3 = __float2half_rn(v3);
                uint32_t hp0 = ((uint32_t)__half_as_ushort(h1) << 16) | __half_as_ushort(h0);
                uint32_t hp1 = ((uint32_t)__half_as_ushort(h3) << 16) | __half_as_ushort(h2);
                uint32_t lp0 = packh(v0 - __half2float(h0), v1 - __half2float(h1));
                uint32_t lp1 = packh(v2 - __half2float(h2), v3 - __half2float(h3));
                *(uint32_t*)(Chi + (size_t)row * Nd + col)       = hp0;
                *(uint32_t*)(Chi + (size_t)(row + 8) * Nd + col) = hp1;
                *(uint32_t*)(Clo + (size_t)row * Nd + col)       = lp0;
                *(uint32_t*)(Clo + (size_t)(row + 8) * Nd + col) = lp1;
            } else {
                float2 o0, o1;
                o0.x = v0; o0.y = v1;
                o1.x = v2; o1.y = v3;
                *(float2*)&Cf[(size_t)row * Nd + col]       = o0;
                *(float2*)&Cf[(size_t)(row + 8) * Nd + col] = o1;
            }
        }
    }
}

// ---------------------------------------------------------------------------
// Tensor-core causal flash attention (fp16 split HMMA):
// S = 3-pass (QhKh + QlKh + QhKl, ~full precision); PV = 2-pass (PhVh + PhVl).
// 128-q tile, 8 warps x 16 rows, 64-key tiles double-buffered.
// Epilogue writes y as single fp16 (stride 1024).
// ---------------------------------------------------------------------------
#define SQH_  0
#define SQL_  (128 * 144)            // 18432
#define SKV0_ (2 * 128 * 144)        // 36864
#define KVBUF_ (4 * 64 * 144)        // 36864 (KH, KL, VH, VL)
#define ATTN_SMEM (SKV0_ + 2 * KVBUF_)   // 110592

__global__ void __launch_bounds__(256, 1)
attn_mma(const __half* __restrict__ qh_g, const __half* __restrict__ ql_g,
         __half* __restrict__ y2)
{
    extern __shared__ char sm[];
    const uint32_t base = smem_u32(sm);
    const int tid  = threadIdx.x;
    const int lane = tid & 31;
    const int wid  = tid >> 5;
    const int qt   = (int)gridDim.x - 1 - (int)blockIdx.x;   // long blocks first
    const int bh   = blockIdx.y;
    const int bb   = bh >> 4;
    const int h    = bh & 15;
    const int qbase = qt * 128;

    // ---- load Q tile hi/lo into smem ----
    {
        const int r  = tid >> 1;
        const int c0 = (tid & 1) * 4;
        const size_t ro = ((size_t)(bb * T_ + qbase + r)) * 3072 + h * 64;
        const uint4* sh = (const uint4*)(qh_g + ro) + c0;
        const uint4* sl = (const uint4*)(ql_g + ro) + c0;
        #pragma unroll
        for (int c = 0; c < 4; ++c) {
            *(uint4*)(sm + SQH_ + r * 144 + (c0 + c) * 16) = sh[c];
            *(uint4*)(sm + SQL_ + r * 144 + (c0 + c) * 16) = sl[c];
        }
    }
    __syncthreads();

    // ---- Q fragments resident in registers for all k tiles ----
    const uint32_t aoff = (uint32_t)((wid * 16 + (lane & 15)) * 144 + (lane >> 4) * 16);
    uint32_t qhf[4][4], qlf[4][4];
    #pragma unroll
    for (int kc = 0; kc < 4; ++kc) {
        ldsm_x4(qhf[kc], base + SQH_ + aoff + kc * 32);
        ldsm_x4(qlf[kc], base + SQL_ + aoff + kc * 32);
    }

    // KV loader mapping: 64 rows x 8 uint4, 256 threads -> 2 uint4/thread/subtile
    const int kr  = tid >> 2;
    const int kc4 = (tid & 3) * 2;
    const int ckq = (1024 + h * 64) >> 3;
    const int cvq = (2048 + h * 64) >> 3;

    float mrow0 = -INFINITY, mrow1 = -INFINITY, lr0 = 0.0f, lr1 = 0.0f;
    float accO[8][4] = {};

    const int nkt = 2 * qt + 2;
    const int qwbase = qbase + wid * 16;
    const int r0g = qwbase + (lane >> 2);
    const float sc = 0.125f;   // 1/sqrt(64)

    uint4 stage[8];
    // load + store tile 0
    {
        const size_t ro = ((size_t)(bb * T_ + kr)) * 3072;
        const uint4* ph = (const uint4*)(qh_g + ro);
        const uint4* pl = (const uint4*)(ql_g + ro);
        stage[0] = ph[ckq + kc4]; stage[1] = ph[ckq + kc4 + 1];
        stage[2] = pl[ckq + kc4]; stage[3] = pl[ckq + kc4 + 1];
        stage[4] = ph[cvq + kc4]; stage[5] = ph[cvq + kc4 + 1];
        stage[6] = pl[cvq + kc4]; stage[7] = pl[cvq + kc4 + 1];
        char* d = sm + SKV0_ + kr * 144 + kc4 * 16;
        *(uint4*)(d)             = stage[0]; *(uint4*)(d + 16)         = stage[1];
        *(uint4*)(d + 9216)      = stage[2]; *(uint4*)(d + 9216 + 16)  = stage[3];
        *(uint4*)(d + 18432)     = stage[4]; *(uint4*)(d + 18432 + 16) = stage[5];
        *(uint4*)(d + 27648)     = stage[6]; *(uint4*)(d + 27648 + 16) = stage[7];
    }
    __syncthreads();

    for (int j = 0; j < nkt; ++j) {
        const int buf = j & 1;
        const int kbase = j * 64;

        if (j + 1 < nkt) {   // prefetch next tile into registers
            const size_t ro = ((size_t)(bb * T_ + (j + 1) * 64 + kr)) * 3072;
            const uint4* ph = (const uint4*)(qh_g + ro);
            const uint4* pl = (const uint4*)(ql_g + ro);
            stage[0] = ph[ckq + kc4]; stage[1] = ph[ckq + kc4 + 1];
            stage[2] = pl[ckq + kc4]; stage[3] = pl[ckq + kc4 + 1];
            stage[4] = ph[cvq + kc4]; stage[5] = ph[cvq + kc4 + 1];
            stage[6] = pl[cvq + kc4]; stage[7] = pl[cvq + kc4 + 1];
        }

        if (kbase <= qwbase + 15) {   // per-warp causal skip
            const uint32_t kvb = base + SKV0_ + buf * KVBUF_;

            // ---- S = Q K^T (3-term split) ----
            float sa[8][4];
            #pragma unroll
            for (int nt = 0; nt < 8; ++nt)
                #pragma unroll
                for (int i = 0; i < 4; ++i) sa[nt][i] = 0.0f;

            #pragma unroll
            for (int kc = 0; kc < 4; ++kc) {
                #pragma unroll
                for (int p = 0; p < 4; ++p) {
                    const uint32_t bo = (uint32_t)((p * 16 + (lane & 7) + ((lane >> 4) & 1) * 8) * 144
                                                   + ((lane >> 3) & 1) * 16 + kc * 32);
                    uint32_t kh[4], kl[4];
                    ldsm_x4(kh, kvb + bo);
                    ldsm_x4(kl, kvb + 9216 + bo);
                    mma_f16(sa[2 * p],     qhf[kc], kh[0], kh[1]);
                    mma_f16(sa[2 * p + 1], qhf[kc], kh[2], kh[3]);
                    mma_f16(sa[2 * p],     qlf[kc], kh[0], kh[1]);
                    mma_f16(sa[2 * p + 1], qlf[kc], kh[2], kh[3]);
                    mma_f16(sa[2 * p],     qhf[kc], kl[0], kl[1]);
                    mma_f16(sa[2 * p + 1], qhf[kc], kl[2], kl[3]);
                }
            }

            // ---- online softmax ----
            const bool diag = (kbase + 63 > qwbase);
            float mx0 = -INFINITY, mx1 = -INFINITY;
            #pragma unroll
            for (int nt = 0; nt < 8; ++nt) {
                const int col = kbase + nt * 8 + (lane & 3) * 2;
                float s0 = sa[nt][0] * sc, s1 = sa[nt][1] * sc;
                float s2 = sa[nt][2] * sc, s3 = sa[nt][3] * sc;
                if (diag) {
                    if (col     > r0g)     s0 = -INFINITY;
                    if (col + 1 > r0g)     s1 = -INFINITY;
                    if (col     > r0g + 8) s2 = -INFINITY;
                    if (col + 1 > r0g + 8) s3 = -INFINITY;
                }
                sa[nt][0] = s0; sa[nt][1] = s1; sa[nt][2] = s2; sa[nt][3] = s3;
                mx0 = fmaxf(mx0, fmaxf(s0, s1));
                mx1 = fmaxf(mx1, fmaxf(s2, s3));
            }
            mx0 = fmaxf(mx0, __shfl_xor_sync(0xffffffffu, mx0, 1));
            mx0 = fmaxf(mx0, __shfl_xor_sync(0xffffffffu, mx0, 2));
            mx1 = fmaxf(mx1, __shfl_xor_sync(0xffffffffu, mx1, 1));
            mx1 = fmaxf(mx1, __shfl_xor_sync(0xffffffffu, mx1, 2));

            const float mn0 = fmaxf(mrow0, mx0), mn1 = fmaxf(mrow1, mx1);
            const float f0 = __expf(mrow0 - mn0), f1 = __expf(mrow1 - mn1);
            mrow0 = mn0; mrow1 = mn1;

            float sum0 = 0.0f, sum1 = 0.0f;
            #pragma unroll
            for (int nt = 0; nt < 8; ++nt) {
                float p0 = __expf(sa[nt][0] - mn0);
                float p1 = __expf(sa[nt][1] - mn0);
                float p2 = __expf(sa[nt][2] - mn1);
                float p3 = __expf(sa[nt][3] - mn1);
                sa[nt][0] = p0; sa[nt][1] = p1; sa[nt][2] = p2; sa[nt][3] = p3;
                sum0 += p0 + p1;
                sum1 += p2 + p3;
            }
            sum0 += __shfl_xor_sync(0xffffffffu, sum0, 1);
            sum0 += __shfl_xor_sync(0xffffffffu, sum0, 2);
            sum1 += __shfl_xor_sync(0xffffffffu, sum1, 1);
            sum1 += __shfl_xor_sync(0xffffffffu, sum1, 2);
            lr0 = lr0 * f0 + sum0;
            lr1 = lr1 * f1 + sum1;
            #pragma unroll
            for (int nt = 0; nt < 8; ++nt) {
                accO[nt][0] *= f0; accO[nt][1] *= f0;
                accO[nt][2] *= f1; accO[nt][3] *= f1;
            }

            // ---- P -> A-fragments (single fp16, register repack) ----
            uint32_t phf[4][4];
            #pragma unroll
            for (int kc = 0; kc < 4; ++kc) {
                #pragma unroll
                for (int half = 0; half < 2; ++half) {
                    const int nt = 2 * kc + half;
                    phf[kc][half * 2 + 0] = packh(sa[nt][0], sa[nt][1]);
                    phf[kc][half * 2 + 1] = packh(sa[nt][2], sa[nt][3]);
                }
            }

            // ---- accO += P V (2-pass: PhVh + PhVl, ldmatrix.trans on V) ----
            const uint32_t voff = (uint32_t)((lane & 15) * 144 + (lane >> 4) * 16);
            #pragma unroll
            for (int kc = 0; kc < 4; ++kc) {
                #pragma unroll
                for (int np = 0; np < 4; ++np) {
                    uint32_t vh[4], vl[4];
                    const uint32_t va = kvb + voff + kc * (16 * 144) + np * 32;
                    ldsm_x4_t(vh, va + 18432);
                    ldsm_x4_t(vl, va + 27648);
                    mma_f16(accO[2 * np],     phf[kc], vh[0], vh[1]);
                    mma_f16(accO[2 * np + 1], phf[kc], vh[2], vh[3]);
                    mma_f16(accO[2 * np],     phf[kc], vl[0], vl[1]);
                    mma_f16(accO[2 * np + 1], phf[kc], vl[2], vl[3]);
                }
            }
        }

        if (j + 1 < nkt) {   // store prefetched tile into the other buffer
            char* d = sm + SKV0_ + (1 - buf) * KVBUF_ + kr * 144 + kc4 * 16;
            *(uint4*)(d)             = stage[0]; *(uint4*)(d + 16)         = stage[1];
            *(uint4*)(d + 9216)      = stage[2]; *(uint4*)(d + 9216 + 16)  = stage[3];
            *(uint4*)(d + 18432)     = stage[4]; *(uint4*)(d + 18432 + 16) = stage[5];
            *(uint4*)(d + 27648)     = stage[6]; *(uint4*)(d + 27648 + 16) = stage[7];
        }
        __syncthreads();
    }

    // ---- epilogue: normalize, write single fp16 (stride 1024) to y2 ----
    const float inv0 = 1.0f / lr0, inv1 = 1.0f / lr1;
    const size_t row0 = (size_t)(bb * T_ + qwbase + (lane >> 2));
    const int colb = h * 64 + (lane & 3) * 2;
    #pragma unroll
    for (int nt = 0; nt < 8; ++nt) {
        const int col = colb + nt * 8;
        uint32_t hp0 = packh(accO[nt][0] * inv0, accO[nt][1] * inv0);
        uint32_t hp1 = packh(accO[nt][2] * inv1, accO[nt][3] * inv1);
        *(uint32_t*)(y2 + row0 * KD1_ + col)       = hp0;
        *(uint32_t*)(y2 + (row0 + 8) * KD1_ + col) = hp1;
    }
}

// ---------------------------------------------------------------------------
// Launch
// ---------------------------------------------------------------------------
extern "C" void kernel_launch(void* const* d_in, const int* in_sizes, int n_in,
                              void* d_out, int out_size)
{
    (void)in_sizes; (void)n_in; (void)out_size;
    const float* x      = (const float*)d_in[0];
    const float* w_attn = (const float*)d_in[1];
    const float* b_attn = (const float*)d_in[2];
    const float* w_proj = (const float*)d_in[3];
    const float* b_proj = (const float*)d_in[4];
    float* out = (float*)d_out;

    __half *x2, *y2, *wa2, *wp2, *qkvh, *qkvl;
    cudaGetSymbolAddress((void**)&x2,   g_x2);
    cudaGetSymbolAddress((void**)&y2,   g_y2);
    cudaGetSymbolAddress((void**)&wa2,  g_wa2);
    cudaGetSymbolAddress((void**)&wp2,  g_wp2);
    cudaGetSymbolAddress((void**)&qkvh, g_qkvh);
    cudaGetSymbolAddress((void**)&qkvl, g_qkvl);

    cudaFuncSetAttribute(attn_mma, cudaFuncAttributeMaxDynamicSharedMemorySize,
                         ATTN_SMEM);
    cudaFuncSetAttribute(gemm_mma<1>, cudaFuncAttributeMaxDynamicSharedMemorySize,
                         GEMM_SMEM);
    cudaFuncSetAttribute(gemm_mma<0>, cudaFuncAttributeMaxDynamicSharedMemorySize,
                         GEMM_SMEM);

    // 1) prologue: scales, snap -> fp16 [hi|lo], x -> fp16
    zero_scales_kernel<<<1, 1>>>();
    maxabs_fused<<<512, 256>>>((const float4*)w_attn, (const float4*)w_proj);
    prep_fused<<<1024, 256>>>((const float4*)w_attn, (const float4*)w_proj,
                              (const float4*)x, wa2, wp2, x2);

    // 2) qkv = x @ snap(w_attn)^T + b_attn  -> fp16 hi/lo
    gemm_mma<1><<<dim3(N3C_ / 128, M_ / 128), 256, GEMM_SMEM>>>(
        x2, wa2, b_attn, nullptr, qkvh, qkvl, N3C_);

    // 3) tensor-core causal flash attention -> y2 (single fp16)
    attn_mma<<<dim3(T_ / 128, B_ * H_), 256, ATTN_SMEM>>>(qkvh, qkvl, y2);

    // 4) out = y @ snap(w_proj)^T + b_proj  (fp32 out)
    gemm_mma<0><<<dim3(C_ / 128, M_ / 128), 256, GEMM_SMEM>>>(
        y2, wp2, b_proj, out, nullptr, nullptr, C_);
}

// round 14
// speedup vs baseline: 2.3651x; 1.5310x over previous
#include <cuda_runtime.h>
#include <cuda_fp16.h>
#include <math.h>
#include <stdint.h>

// Problem constants
#define B_   2
#define T_   2048
#define C_   1024
#define H_   16
#define M_   (B_ * T_)      // 4096
#define N3C_ (3 * C_)       // 3072
#define KD1_ 1024           // single-fp16 K width

// ---------------------------------------------------------------------------
// Helpers
// ---------------------------------------------------------------------------
__device__ __forceinline__ uint32_t smem_u32(const void* p) {
    uint32_t a;
    asm("{ .reg .u64 t; cvta.to.shared.u64 t, %1; cvt.u32.u64 %0, t; }"
        : "=r"(a) : "l"(p));
    return a;
}

__device__ __forceinline__ void ldsm_x4(uint32_t (&r)[4], uint32_t addr) {
    asm volatile("ldmatrix.sync.aligned.m8n8.x4.shared.b16 {%0,%1,%2,%3}, [%4];"
                 : "=r"(r[0]), "=r"(r[1]), "=r"(r[2]), "=r"(r[3]) : "r"(addr));
}

__device__ __forceinline__ void ldsm_x4_t(uint32_t (&r)[4], uint32_t addr) {
    asm volatile("ldmatrix.sync.aligned.m8n8.x4.trans.shared.b16 {%0,%1,%2,%3}, [%4];"
                 : "=r"(r[0]), "=r"(r[1]), "=r"(r[2]), "=r"(r[3]) : "r"(addr));
}

__device__ __forceinline__ void mma_f16(float (&c)[4], const uint32_t (&a)[4],
                                        uint32_t b0, uint32_t b1) {
    asm volatile(
        "mma.sync.aligned.m16n8k16.row.col.f32.f16.f16.f32 "
        "{%0,%1,%2,%3}, {%4,%5,%6,%7}, {%8,%9}, {%0,%1,%2,%3};"
        : "+f"(c[0]), "+f"(c[1]), "+f"(c[2]), "+f"(c[3])
        : "r"(a[0]), "r"(a[1]), "r"(a[2]), "r"(a[3]), "r"(b0), "r"(b1));
}

// pack two f32 -> f16x2, first arg in lower half
__device__ __forceinline__ uint32_t packh(float lo, float hi) {
    uint32_t u;
    asm("cvt.rn.f16x2.f32 %0, %1, %2;" : "=r"(u) : "f"(hi), "f"(lo));
    return u;
}

__device__ __forceinline__ void cp16(uint32_t dst, const void* src) {
    asm volatile("cp.async.cg.shared.global [%0], [%1], 16;"
                 :: "r"(dst), "l"(src) : "memory");
}
#define CP_COMMIT() asm volatile("cp.async.commit_group;" ::: "memory")
#define CP_WAIT1()  asm volatile("cp.async.wait_group 1;" ::: "memory")
#define CP_WAIT0()  asm volatile("cp.async.wait_group 0;" ::: "memory")

// ---------------------------------------------------------------------------
// Scratch (device globals)
// ---------------------------------------------------------------------------
__device__ __half g_x2[(size_t)M_ * KD1_];    // x  fp16
__device__ __half g_y2[(size_t)M_ * KD1_];    // attn out fp16
__device__ __half g_wa2[(size_t)N3C_ * KD1_]; // snap(w_attn) fp16
__device__ __half g_wp2[(size_t)C_ * KD1_];   // snap(w_proj) fp16
__device__ __half g_qkv[(size_t)M_ * N3C_];   // qkv fp16
__device__ unsigned int g_maxbits[2];

// ---------------------------------------------------------------------------
// Prologue (exact argmin + exact division)
// ---------------------------------------------------------------------------
__global__ void zero_scales_kernel() { g_maxbits[0] = 0u; g_maxbits[1] = 0u; }

__device__ __forceinline__ void maxabs_body(const float4* __restrict__ w,
                                            int n4, int slot, int b0, int nb) {
    float m = 0.0f;
    for (int i = b0 * 256 + threadIdx.x; i < n4; i += nb * 256) {
        float4 v = w[i];
        m = fmaxf(m, fmaxf(fmaxf(fabsf(v.x), fabsf(v.y)),
                           fmaxf(fabsf(v.z), fabsf(v.w))));
    }
    #pragma unroll
    for (int o = 16; o > 0; o >>= 1)
        m = fmaxf(m, __shfl_xor_sync(0xffffffffu, m, o));
    __shared__ float sm[8];
    int lane = threadIdx.x & 31, wd = threadIdx.x >> 5;
    if (lane == 0) sm[wd] = m;
    __syncthreads();
    if (threadIdx.x < 8) {
        m = sm[threadIdx.x];
        #pragma unroll
        for (int o = 4; o > 0; o >>= 1)
            m = fmaxf(m, __shfl_xor_sync(0xffu, m, o));
        if (threadIdx.x == 0)
            atomicMax(&g_maxbits[slot], __float_as_uint(m));
    }
}

__global__ void __launch_bounds__(256) maxabs_fused(const float4* __restrict__ wa,
                                                    const float4* __restrict__ wp) {
    const int bx = blockIdx.x;
    if (bx < 384) maxabs_body(wa, (N3C_ * C_) / 4, 0, bx, 384);
    else          maxabs_body(wp, (C_ * C_) / 4, 1, bx - 384, 128);
}

// exact argmin over the 16-entry LUT (reference order, strict < tie-break)
__device__ __forceinline__ float snap1(float wn, float scale) {
    const float L1 = 1.0f,      L3 = 0.5f,      L5 = 0.333333f, L7 = 0.2f,
                L9 = 0.142857f, L11 = 0.090909f, L13 = 0.076923f;
    float bd = fabsf(wn);       // LUT[0] = 0
    float bv = 0.0f;
    #define TRY_(val) { float d_ = fabsf(wn - (val)); if (d_ < bd) { bd = d_; bv = (val); } }
    TRY_(L1)  TRY_(-L1)  TRY_(L3)  TRY_(-L3)  TRY_(L5)  TRY_(-L5)  TRY_(L7)
    TRY_(-L7) TRY_(L9)   TRY_(-L9) TRY_(L11)  TRY_(-L11) TRY_(L13) TRY_(-L13)
    #undef TRY_
    return bv * scale;
}

__device__ __forceinline__ void snap_body(const float4* __restrict__ w,
                                          __half* __restrict__ out,
                                          int n4, int slot, int b0, int nb) {
    const float scale = __uint_as_float(g_maxbits[slot]) + 1e-6f;
    for (int i = b0 * 256 + threadIdx.x; i < n4; i += nb * 256) {
        float4 wv = w[i];
        float v0 = snap1(wv.x / scale, scale);
        float v1 = snap1(wv.y / scale, scale);
        float v2 = snap1(wv.z / scale, scale);
        float v3 = snap1(wv.w / scale, scale);
        *(uint2*)(out + (size_t)i * 4) = make_uint2(packh(v0, v1), packh(v2, v3));
    }
}

__device__ __forceinline__ void cvt_body(const float4* __restrict__ a,
                                         __half* __restrict__ out,
                                         int n4, int b0, int nb) {
    for (int i = b0 * 256 + threadIdx.x; i < n4; i += nb * 256) {
        float4 v = a[i];
        *(uint2*)(out + (size_t)i * 4) = make_uint2(packh(v.x, v.y), packh(v.z, v.w));
    }
}

__global__ void __launch_bounds__(256) prep_fused(
    const float4* __restrict__ wa, const float4* __restrict__ wp,
    const float4* __restrict__ x,
    __half* __restrict__ wa2, __half* __restrict__ wp2,
    __half* __restrict__ x2)
{
    const int bx = blockIdx.x;
    if (bx < 448)       snap_body(wa, wa2, (N3C_ * C_) / 4, 0, bx, 448);
    else if (bx < 576)  snap_body(wp, wp2, (C_ * C_) / 4, 1, bx - 448, 128);
    else                cvt_body(x, x2, (M_ * C_) / 4, bx - 576, 448);
}

// ---------------------------------------------------------------------------
// fp16 single-pass mma.sync GEMM: C = A(fp16,K=1024) @ B(fp16,K=1024)^T + bias
// 128x128 tile, BK=32, 8 warps (2m x 4n), cp.async 3-stage ring, 1 barrier/iter.
// SPLIT=1: fp16 out; SPLIT=0: fp32 out.
// ---------------------------------------------------------------------------
#define GP_    80                    // smem row stride (bytes)
#define GT_    (128 * GP_)           // 10240 per matrix per stage
#define GSTAGE (2 * GT_)             // 20480 per stage (A,B)
#define GEMM_SMEM (3 * GSTAGE)       // 61440
#define GNIT_  32                    // 1024 / 32

template <int SPLIT>
__global__ void __launch_bounds__(256, 2)
gemm_mma(const __half* __restrict__ A2, const __half* __restrict__ B2,
         const float* __restrict__ bias, float* __restrict__ Cf,
         __half* __restrict__ Ch, int Nd)
{
    extern __shared__ char gsm[];
    const uint32_t sbase = smem_u32(gsm);
    const int tid  = threadIdx.x;
    const int lane = tid & 31;
    const int wid  = tid >> 5;
    const int wm   = wid >> 2;
    const int wn   = wid & 3;
    const int m0   = blockIdx.y * 128;
    const int n0   = blockIdx.x * 128;

    // loader: 2 threads/row; each thread covers 2 x 16B chunks per matrix
    const int lr  = tid >> 1;
    const int lc2 = (tid & 1) * 2;
    const __half* gA = A2 + (size_t)(m0 + lr) * KD1_;
    const __half* gB = B2 + (size_t)(n0 + lr) * KD1_;
    const uint32_t soff = (uint32_t)(lr * GP_ + lc2 * 16);

    const uint32_t aoff = (uint32_t)((wm * 64 + (lane & 15)) * GP_ + (lane >> 4) * 16);
    const uint32_t boff = (uint32_t)((wn * 32 + (lane & 7) + ((lane >> 4) & 1) * 8) * GP_
                                     + ((lane >> 3) & 1) * 16);

    float acc[4][4][4] = {};

    auto issue = [&](int it) {
        const uint32_t sb = sbase + (it % 3) * GSTAGE + soff;
        const int k0 = it * 32 + lc2 * 8;
        cp16(sb,            gA + k0);
        cp16(sb + 16,       gA + k0 + 8);
        cp16(sb + GT_,      gB + k0);
        cp16(sb + GT_ + 16, gB + k0 + 8);
        CP_COMMIT();
    };

    issue(0);
    issue(1);

    for (int it = 0; it < GNIT_; ++it) {
        if (it + 1 < GNIT_) { CP_WAIT1(); } else { CP_WAIT0(); }
        __syncthreads();
        if (it + 2 < GNIT_) issue(it + 2);   // slot (it+2)%3 last read at it-1

        const uint32_t sb = sbase + (it % 3) * GSTAGE;
        #pragma unroll
        for (int ks = 0; ks < 2; ++ks) {
            const uint32_t kso = (uint32_t)(ks * 32);
            uint32_t b0[4], b1[4], af[4][4];
            ldsm_x4(b0, sb + GT_ + boff + kso);
            ldsm_x4(b1, sb + GT_ + boff + 16 * GP_ + kso);
            #pragma unroll
            for (int mt = 0; mt < 4; ++mt)
                ldsm_x4(af[mt], sb + aoff + mt * (16 * GP_) + kso);
            #pragma unroll
            for (int mt = 0; mt < 4; ++mt) {
                mma_f16(acc[mt][0], af[mt], b0[0], b0[1]);
                mma_f16(acc[mt][1], af[mt], b0[2], b0[3]);
                mma_f16(acc[mt][2], af[mt], b1[0], b1[1]);
                mma_f16(acc[mt][3], af[mt], b1[2], b1[3]);
            }
        }
    }

    #pragma unroll
    for (int nt = 0; nt < 4; ++nt) {
        const int col = n0 + wn * 32 + nt * 8 + (lane & 3) * 2;
        const float bv0 = bias[col];
        const float bv1 = bias[col + 1];
        #pragma unroll
        for (int mt = 0; mt < 4; ++mt) {
            const int row = m0 + wm * 64 + mt * 16 + (lane >> 2);
            float v0 = acc[mt][nt][0] + bv0, v1 = acc[mt][nt][1] + bv1;
            float v2 = acc[mt][nt][2] + bv0, v3 = acc[mt][nt][3] + bv1;
            if (SPLIT) {
                *(uint32_t*)(Ch + (size_t)row * Nd + col)       = packh(v0, v1);
                *(uint32_t*)(Ch + (size_t)(row + 8) * Nd + col) = packh(v2, v3);
            } else {
                float2 o0, o1;
                o0.x = v0; o0.y = v1;
                o1.x = v2; o1.y = v3;
                *(float2*)&Cf[(size_t)row * Nd + col]       = o0;
                *(float2*)&Cf[(size_t)(row + 8) * Nd + col] = o1;
            }
        }
    }
}

// ---------------------------------------------------------------------------
// fp16 causal flash attention: single-pass S = QK^T, single-pass PV.
// 128-q tile, 8 warps x 16 rows, 64-key tiles double-buffered, occ 2.
// ---------------------------------------------------------------------------
#define SQ_    0
#define SKV0_  (128 * 144)           // 18432
#define KVB2_  (2 * 64 * 144)        // 18432 (K, V)
#define ATTN_SMEM (SKV0_ + 2 * KVB2_)    // 55296

__global__ void __launch_bounds__(256, 2)
attn_mma(const __half* __restrict__ qkv, __half* __restrict__ y2)
{
    extern __shared__ char sm[];
    const uint32_t base = smem_u32(sm);
    const int tid  = threadIdx.x;
    const int lane = tid & 31;
    const int wid  = tid >> 5;
    const int qt   = (int)gridDim.x - 1 - (int)blockIdx.x;   // long blocks first
    const int bh   = blockIdx.y;
    const int bb   = bh >> 4;
    const int h    = bh & 15;
    const int qbase = qt * 128;

    // ---- load Q tile into smem ----
    {
        const int r  = tid >> 1;
        const int c0 = (tid & 1) * 4;
        const size_t ro = ((size_t)(bb * T_ + qbase + r)) * 3072 + h * 64;
        const uint4* sq = (const uint4*)(qkv + ro) + c0;
        #pragma unroll
        for (int c = 0; c < 4; ++c)
            *(uint4*)(sm + SQ_ + r * 144 + (c0 + c) * 16) = sq[c];
    }
    __syncthreads();

    // ---- Q fragments resident in registers ----
    const uint32_t aoff = (uint32_t)((wid * 16 + (lane & 15)) * 144 + (lane >> 4) * 16);
    uint32_t qf[4][4];
    #pragma unroll
    for (int kc = 0; kc < 4; ++kc)
        ldsm_x4(qf[kc], base + SQ_ + aoff + kc * 32);

    // KV loader mapping: 64 rows x 8 uint4 per matrix, 256 threads
    const int kr  = tid >> 2;
    const int kc4 = (tid & 3) * 2;
    const int ckq = (1024 + h * 64) >> 3;
    const int cvq = (2048 + h * 64) >> 3;

    float mrow0 = -INFINITY, mrow1 = -INFINITY, lr0 = 0.0f, lr1 = 0.0f;
    float accO[8][4] = {};

    const int nkt = 2 * qt + 2;
    const int qwbase = qbase + wid * 16;
    const int r0g = qwbase + (lane >> 2);
    const float sc = 0.125f;   // 1/sqrt(64)

    uint4 stage[4];
    // load + store tile 0
    {
        const size_t ro = ((size_t)(bb * T_ + kr)) * 3072;
        const uint4* pq = (const uint4*)(qkv + ro);
        stage[0] = pq[ckq + kc4]; stage[1] = pq[ckq + kc4 + 1];
        stage[2] = pq[cvq + kc4]; stage[3] = pq[cvq + kc4 + 1];
        char* d = sm + SKV0_ + kr * 144 + kc4 * 16;
        *(uint4*)(d)            = stage[0]; *(uint4*)(d + 16)        = stage[1];
        *(uint4*)(d + 9216)     = stage[2]; *(uint4*)(d + 9216 + 16) = stage[3];
    }
    __syncthreads();

    for (int j = 0; j < nkt; ++j) {
        const int buf = j & 1;
        const int kbase = j * 64;

        if (j + 1 < nkt) {   // prefetch next tile into registers
            const size_t ro = ((size_t)(bb * T_ + (j + 1) * 64 + kr)) * 3072;
            const uint4* pq = (const uint4*)(qkv + ro);
            stage[0] = pq[ckq + kc4]; stage[1] = pq[ckq + kc4 + 1];
            stage[2] = pq[cvq + kc4]; stage[3] = pq[cvq + kc4 + 1];
        }

        if (kbase <= qwbase + 15) {   // per-warp causal skip
            const uint32_t kvb = base + SKV0_ + buf * KVB2_;

            // ---- S = Q K^T (single pass) ----
            float sa[8][4];
            #pragma unroll
            for (int nt = 0; nt < 8; ++nt)
                #pragma unroll
                for (int i = 0; i < 4; ++i) sa[nt][i] = 0.0f;

            #pragma unroll
            for (int kc = 0; kc < 4; ++kc) {
                #pragma unroll
                for (int p = 0; p < 4; ++p) {
                    const uint32_t bo = (uint32_t)((p * 16 + (lane & 7) + ((lane >> 4) & 1) * 8) * 144
                                                   + ((lane >> 3) & 1) * 16 + kc * 32);
                    uint32_t kf[4];
                    ldsm_x4(kf, kvb + bo);
                    mma_f16(sa[2 * p],     qf[kc], kf[0], kf[1]);
                    mma_f16(sa[2 * p + 1], qf[kc], kf[2], kf[3]);
                }
            }

            // ---- online softmax ----
            const bool diag = (kbase + 63 > qwbase);
            float mx0 = -INFINITY, mx1 = -INFINITY;
            #pragma unroll
            for (int nt = 0; nt < 8; ++nt) {
                const int col = kbase + nt * 8 + (lane & 3) * 2;
                float s0 = sa[nt][0] * sc, s1 = sa[nt][1] * sc;
                float s2 = sa[nt][2] * sc, s3 = sa[nt][3] * sc;
                if (diag) {
                    if (col     > r0g)     s0 = -INFINITY;
                    if (col + 1 > r0g)     s1 = -INFINITY;
                    if (col     > r0g + 8) s2 = -INFINITY;
                    if (col + 1 > r0g + 8) s3 = -INFINITY;
                }
                sa[nt][0] = s0; sa[nt][1] = s1; sa[nt][2] = s2; sa[nt][3] = s3;
                mx0 = fmaxf(mx0, fmaxf(s0, s1));
                mx1 = fmaxf(mx1, fmaxf(s2, s3));
            }
            mx0 = fmaxf(mx0, __shfl_xor_sync(0xffffffffu, mx0, 1));
            mx0 = fmaxf(mx0, __shfl_xor_sync(0xffffffffu, mx0, 2));
            mx1 = fmaxf(mx1, __shfl_xor_sync(0xffffffffu, mx1, 1));
            mx1 = fmaxf(mx1, __shfl_xor_sync(0xffffffffu, mx1, 2));

            const float mn0 = fmaxf(mrow0, mx0), mn1 = fmaxf(mrow1, mx1);
            const float f0 = __expf(mrow0 - mn0), f1 = __expf(mrow1 - mn1);
            mrow0 = mn0; mrow1 = mn1;

            float sum0 = 0.0f, sum1 = 0.0f;
            #pragma unroll
            for (int nt = 0; nt < 8; ++nt) {
                float p0 = __expf(sa[nt][0] - mn0);
                float p1 = __expf(sa[nt][1] - mn0);
                float p2 = __expf(sa[nt][2] - mn1);
                float p3 = __expf(sa[nt][3] - mn1);
                sa[nt][0] = p0; sa[nt][1] = p1; sa[nt][2] = p2; sa[nt][3] = p3;
                sum0 += p0 + p1;
                sum1 += p2 + p3;
            }
            sum0 += __shfl_xor_sync(0xffffffffu, sum0, 1);
            sum0 += __shfl_xor_sync(0xffffffffu, sum0, 2);
            sum1 += __shfl_xor_sync(0xffffffffu, sum1, 1);
            sum1 += __shfl_xor_sync(0xffffffffu, sum1, 2);
            lr0 = lr0 * f0 + sum0;
            lr1 = lr1 * f1 + sum1;
            #pragma unroll
            for (int nt = 0; nt < 8; ++nt) {
                accO[nt][0] *= f0; accO[nt][1] *= f0;
                accO[nt][2] *= f1; accO[nt][3] *= f1;
            }

            // ---- P -> A-fragments (fp16, register repack) ----
            uint32_t pf[4][4];
            #pragma unroll
            for (int kc = 0; kc < 4; ++kc) {
                #pragma unroll
                for (int half = 0; half < 2; ++half) {
                    const int nt = 2 * kc + half;
                    pf[kc][half * 2 + 0] = packh(sa[nt][0], sa[nt][1]);
                    pf[kc][half * 2 + 1] = packh(sa[nt][2], sa[nt][3]);
                }
            }

            // ---- accO += P V (single pass, ldmatrix.trans on V) ----
            const uint32_t voff = (uint32_t)((lane & 15) * 144 + (lane >> 4) * 16);
            #pragma unroll
            for (int kc = 0; kc < 4; ++kc) {
                #pragma unroll
                for (int np = 0; np < 4; ++np) {
                    uint32_t vf[4];
                    ldsm_x4_t(vf, kvb + 9216 + voff + kc * (16 * 144) + np * 32);
                    mma_f16(accO[2 * np],     pf[kc], vf[0], vf[1]);
                    mma_f16(accO[2 * np + 1], pf[kc], vf[2], vf[3]);
                }
            }
        }

        if (j + 1 < nkt) {   // store prefetched tile into the other buffer
            char* d = sm + SKV0_ + (1 - buf) * KVB2_ + kr * 144 + kc4 * 16;
            *(uint4*)(d)            = stage[0]; *(uint4*)(d + 16)        = stage[1];
            *(uint4*)(d + 9216)     = stage[2]; *(uint4*)(d + 9216 + 16) = stage[3];
        }
        __syncthreads();
    }

    // ---- epilogue: normalize, write fp16 y (stride 1024) ----
    const float inv0 = 1.0f / lr0, inv1 = 1.0f / lr1;
    const size_t row0 = (size_t)(bb * T_ + qwbase + (lane >> 2));
    const int colb = h * 64 + (lane & 3) * 2;
    #pragma unroll
    for (int nt = 0; nt < 8; ++nt) {
        const int col = colb + nt * 8;
        *(uint32_t*)(y2 + row0 * KD1_ + col)       = packh(accO[nt][0] * inv0, accO[nt][1] * inv0);
        *(uint32_t*)(y2 + (row0 + 8) * KD1_ + col) = packh(accO[nt][2] * inv1, accO[nt][3] * inv1);
    }
}

// ---------------------------------------------------------------------------
// Launch
// ---------------------------------------------------------------------------
extern "C" void kernel_launch(void* const* d_in, const int* in_sizes, int n_in,
                              void* d_out, int out_size)
{
    (void)in_sizes; (void)n_in; (void)out_size;
    const float* x      = (const float*)d_in[0];
    const float* w_attn = (const float*)d_in[1];
    const float* b_attn = (const float*)d_in[2];
    const float* w_proj = (const float*)d_in[3];
    const float* b_proj = (const float*)d_in[4];
    float* out = (float*)d_out;

    __half *x2, *y2, *wa2, *wp2, *qkv;
    cudaGetSymbolAddress((void**)&x2,  g_x2);
    cudaGetSymbolAddress((void**)&y2,  g_y2);
    cudaGetSymbolAddress((void**)&wa2, g_wa2);
    cudaGetSymbolAddress((void**)&wp2, g_wp2);
    cudaGetSymbolAddress((void**)&qkv, g_qkv);

    cudaFuncSetAttribute(attn_mma, cudaFuncAttributeMaxDynamicSharedMemorySize,
                         ATTN_SMEM);
    cudaFuncSetAttribute(gemm_mma<1>, cudaFuncAttributeMaxDynamicSharedMemorySize,
                         GEMM_SMEM);
    cudaFuncSetAttribute(gemm_mma<0>, cudaFuncAttributeMaxDynamicSharedMemorySize,
                         GEMM_SMEM);

    // 1) prologue: scales, snap -> fp16, x -> fp16
    zero_scales_kernel<<<1, 1>>>();
    maxabs_fused<<<512, 256>>>((const float4*)w_attn, (const float4*)w_proj);
    prep_fused<<<1024, 256>>>((const float4*)w_attn, (const float4*)w_proj,
                              (const float4*)x, wa2, wp2, x2);

    // 2) qkv = x @ snap(w_attn)^T + b_attn  (single-pass fp16)
    gemm_mma<1><<<dim3(N3C_ / 128, M_ / 128), 256, GEMM_SMEM>>>(
        x2, wa2, b_attn, nullptr, qkv, N3C_);

    // 3) causal flash attention -> y2 (fp16)
    attn_mma<<<dim3(T_ / 128, B_ * H_), 256, ATTN_SMEM>>>(qkv, y2);

    // 4) out = y @ snap(w_proj)^T + b_proj  (fp32 out)
    gemm_mma<0><<<dim3(C_ / 128, M_ / 128), 256, GEMM_SMEM>>>(
        y2, wp2, b_proj, out, nullptr, C_);
}